// round 1
// baseline (speedup 1.0000x reference)
#include <cuda_runtime.h>
#include <math.h>

#define BB 2
#define SS 2048
#define HH 16
#define DD 128
#define HIDN 2048
#define BHS (BB*HH*SS)          // 65536 rows of length D

// ---------------- scratch (static device globals; no allocation) ----------------
__device__ float g_q  [BB*HH*SS*DD];
__device__ float g_k  [BB*HH*SS*DD];
__device__ float g_v  [BB*HH*SS*DD];
__device__ float g_sq [BB*HH*SS*DD];
__device__ float g_sk [BB*HH*SS*DD];
__device__ float g_mem[BB*HH*SS*DD];
__device__ float g_att[BB*HH*SS*DD];
__device__ float g_mpart[HH*16*DD*DD];
__device__ float g_zpart[HH*16*DD];

// ---------------- QKV projection: C = hidden @ W + b, written [b,h,s,d] ----------------
__global__ __launch_bounds__(256) void gemm_qkv_kernel(
    const float* __restrict__ A,
    const float* __restrict__ Wq, const float* __restrict__ Wk, const float* __restrict__ Wv,
    const float* __restrict__ bq, const float* __restrict__ bk, const float* __restrict__ bv)
{
    __shared__ float As[128][20];   // [m][k] natural, pad 4
    __shared__ float Bs[16][132];   // [k][n] natural, pad 4
    int which = blockIdx.z;
    const float* W    = (which==0)?Wq:((which==1)?Wk:Wv);
    const float* bias = (which==0)?bq:((which==1)?bk:bv);
    float* O          = (which==0)?g_q:((which==1)?g_k:g_v);
    int m0 = blockIdx.y*128, n0 = blockIdx.x*128;
    int t = threadIdx.x, ty = t>>4, tx = t&15;
    float acc[8][8];
    #pragma unroll
    for (int i=0;i<8;i++)
        #pragma unroll
        for (int j=0;j<8;j++) acc[i][j]=0.f;

    for (int k0=0;k0<HIDN;k0+=16){
        #pragma unroll
        for (int i=0;i<2;i++){
            int idx = t + i*256;
            int r  = idx>>2, c4  = idx&3;
            float4 va = *(const float4*)(A + (size_t)(m0+r)*HIDN + k0 + c4*4);
            *(float4*)(&As[r][c4*4]) = va;
            int r2 = idx>>5, c42 = idx&31;
            float4 vb = *(const float4*)(W + (size_t)(k0+r2)*HIDN + n0 + c42*4);
            *(float4*)(&Bs[r2][c42*4]) = vb;
        }
        __syncthreads();
        #pragma unroll
        for (int kk=0;kk<16;kk++){
            float ra[8], rb[8];
            #pragma unroll
            for (int i=0;i<8;i++) ra[i] = As[i*16+ty][kk];
            #pragma unroll
            for (int j=0;j<8;j++) rb[j] = Bs[kk][j*16+tx];
            #pragma unroll
            for (int i=0;i<8;i++)
                #pragma unroll
                for (int j=0;j<8;j++) acc[i][j] += ra[i]*rb[j];
        }
        __syncthreads();
    }
    #pragma unroll
    for (int i=0;i<8;i++){
        int m = m0 + i*16+ty;
        int b = m>>11, s = m&2047;
        #pragma unroll
        for (int j=0;j<8;j++){
            int n = n0 + j*16+tx;
            int h = n>>7, d = n&127;
            O[(((size_t)(b*HH+h))*SS + s)*DD + d] = acc[i][j] + bias[n];
        }
    }
}

// ---------------- RoPE + sigma(elu+1); in-place q/k, writes sig_q/sig_k ----------------
__global__ __launch_bounds__(256) void rope_kernel(const int* __restrict__ pos)
{
    int t = threadIdx.x;
    long rid = (long)blockIdx.x*2 + (t>>7);   // row over (b,h,s)
    int d = t & 127;
    int s  = (int)(rid & (SS-1));
    int bh = (int)(rid >> 11);
    int b  = bh >> 4;
    size_t base = (size_t)rid * DD;
    float qv = g_q[base+d], kv = g_k[base+d];
    float qo = (d<64)? -g_q[base+d+64] : g_q[base+d-64];
    float ko = (d<64)? -g_k[base+d+64] : g_k[base+d-64];
    int p = pos[(size_t)b*SS + s];
    // inv_freq = exp(-(2i/128)*ln(10000)), i = d%64
    float inv = expf(-0.14391156831212787f * (float)(d & 63));
    float ang = (float)p * inv;
    float sn, cs;
    sincosf(ang, &sn, &cs);
    float qn = qv*cs + qo*sn;
    float kn = kv*cs + ko*sn;
    __syncthreads();   // all reads of this row done before overwrite
    g_q[base+d] = qn;
    g_k[base+d] = kn;
    g_sq[base+d] = (qn>0.f) ? qn+1.f : expf(qn);
    g_sk[base+d] = (kn>0.f) ? kn+1.f : expf(kn);
}

// ---------------- memory retrieval: (sig_q @ M[h]) / (sig_q . z[h]) ----------------
__global__ __launch_bounds__(256) void memret_kernel(
    const float* __restrict__ M, const float* __restrict__ z)
{
    extern __shared__ float sm[];
    float* Sq = sm;             // [128][132]  sig_q rows
    float* Ms = Sq + 128*132;   // [128][132]  M[h] (d-major)
    float* zs = Ms + 128*132;   // [128]
    int s0 = blockIdx.x * 128;
    int bh = blockIdx.y;
    int h  = bh & 15;
    int t = threadIdx.x, ty=t>>4, tx=t&15;
    size_t base = (size_t)bh*SS*DD + (size_t)s0*DD;
    #pragma unroll
    for (int i=0;i<16;i++){
        int idx = t + i*256; int r = idx>>5, c4 = idx&31;
        *(float4*)(&Sq[r*132 + c4*4]) = *(const float4*)(g_sq + base + (size_t)r*DD + c4*4);
        *(float4*)(&Ms[r*132 + c4*4]) = *(const float4*)(M + (size_t)h*DD*DD + (size_t)r*DD + c4*4);
    }
    if (t < 128) zs[t] = z[h*DD + t];
    __syncthreads();

    float acc[8][8], den[8];
    #pragma unroll
    for (int i=0;i<8;i++){
        den[i]=0.f;
        #pragma unroll
        for (int j=0;j<8;j++) acc[i][j]=0.f;
    }
    for (int d=0; d<128; d++){
        float zv = zs[d];
        float rq[8], rm[8];
        #pragma unroll
        for (int i=0;i<8;i++) rq[i] = Sq[(i*16+ty)*132 + d];
        #pragma unroll
        for (int j=0;j<8;j++) rm[j] = Ms[d*132 + j*16+tx];
        #pragma unroll
        for (int i=0;i<8;i++){
            den[i] += rq[i]*zv;
            #pragma unroll
            for (int j=0;j<8;j++) acc[i][j] += rq[i]*rm[j];
        }
    }
    #pragma unroll
    for (int i=0;i<8;i++){
        float dinv = 1.f/den[i];
        #pragma unroll
        for (int j=0;j<8;j++)
            g_mem[base + (size_t)(i*16+ty)*DD + j*16+tx] = acc[i][j]*dinv;
    }
}

// ---------------- causal flash attention (fp32) ----------------
__global__ __launch_bounds__(256) void attn_flash_kernel()
{
    extern __shared__ float sm[];
    float* Qs  = sm;                  // [128][132] rows natural
    float* Ks  = Qs + 128*132;        // [128][64]  d-major, XOR-swizzled cols
    float* Vs  = Ks + 128*64;         // [64][132]  rows natural
    float* Ps  = Vs + 64*132;         // [128][65]
    float* mrow= Ps + 128*65;         // [128]
    float* lrow= mrow + 128;
    float* rs  = lrow + 128;
    int qb = blockIdx.x;
    int bh = blockIdx.y;
    int t = threadIdx.x, ty = t>>4, tx = t&15;
    size_t base = (size_t)bh * SS * DD;

    #pragma unroll
    for (int i=0;i<16;i++){
        int idx = t + i*256; int r = idx>>5, c4 = idx&31;
        *(float4*)(&Qs[r*132 + c4*4]) =
            *(const float4*)(g_q + base + (size_t)(qb*128 + r)*DD + c4*4);
    }
    if (t < 128){ mrow[t] = -INFINITY; lrow[t] = 0.f; }
    float acc[8][8];
    #pragma unroll
    for (int i=0;i<8;i++)
        #pragma unroll
        for (int j=0;j<8;j++) acc[i][j]=0.f;
    __syncthreads();

    const float sscale = 0.08838834764831845f;  // 1/sqrt(128)
    int jbmax = 2*qb + 1;
    for (int jb=0;jb<=jbmax;jb++){
        // K (swizzled transpose) + V (natural)
        #pragma unroll
        for (int i=0;i<8;i++){
            int idx = t + i*256; int r = idx>>5, c4 = idx&31;
            size_t g = base + (size_t)(jb*64 + r)*DD + c4*4;
            float4 kk4 = *(const float4*)(g_k + g);
            int sw = r ^ c4;
            Ks[(4*c4+0)*64 + sw] = kk4.x;
            Ks[(4*c4+1)*64 + sw] = kk4.y;
            Ks[(4*c4+2)*64 + sw] = kk4.z;
            Ks[(4*c4+3)*64 + sw] = kk4.w;
            *(float4*)(&Vs[r*132 + c4*4]) = *(const float4*)(g_v + g);
        }
        __syncthreads();

        // S = Q K^T
        float sacc[8][4];
        #pragma unroll
        for (int i=0;i<8;i++)
            #pragma unroll
            for (int j=0;j<4;j++) sacc[i][j]=0.f;
        for (int d=0; d<128; d++){
            float rq[8], rk[4];
            int c = d>>2;
            #pragma unroll
            for (int ii=0;ii<8;ii++) rq[ii] = Qs[(ii*16+ty)*132 + d];
            #pragma unroll
            for (int jj=0;jj<4;jj++) rk[jj] = Ks[d*64 + ((jj*16+tx)^c)];
            #pragma unroll
            for (int ii=0;ii<8;ii++)
                #pragma unroll
                for (int jj=0;jj<4;jj++) sacc[ii][jj] += rq[ii]*rk[jj];
        }
        #pragma unroll
        for (int ii=0;ii<8;ii++){
            int i = ii*16+ty;
            int qrow = qb*128 + i;
            #pragma unroll
            for (int jj=0;jj<4;jj++){
                int j = jj*16+tx;
                int kcol = jb*64 + j;
                Ps[i*65 + j] = (kcol <= qrow) ? sacc[ii][jj]*sscale : -INFINITY;
            }
        }
        __syncthreads();

        // online softmax per row
        if (t < 128){
            float m_old = mrow[t], l_old = lrow[t];
            float tmax = -INFINITY;
            #pragma unroll 8
            for (int j=0;j<64;j++) tmax = fmaxf(tmax, Ps[t*65+j]);
            float m_new = fmaxf(m_old, tmax);
            float sc = __expf(m_old - m_new);
            float sum = 0.f;
            #pragma unroll 8
            for (int j=0;j<64;j++){
                float p = __expf(Ps[t*65+j] - m_new);
                Ps[t*65+j] = p;
                sum += p;
            }
            mrow[t] = m_new;
            lrow[t] = sc*l_old + sum;
            rs[t]   = sc;
        }
        __syncthreads();

        // rescale + P @ V
        {
            float scl[8];
            #pragma unroll
            for (int ii=0;ii<8;ii++) scl[ii] = rs[ii*16+ty];
            #pragma unroll
            for (int ii=0;ii<8;ii++)
                #pragma unroll
                for (int ee=0;ee<8;ee++) acc[ii][ee] *= scl[ii];
            for (int j=0;j<64;j++){
                float rp[8], rv[8];
                #pragma unroll
                for (int ii=0;ii<8;ii++) rp[ii] = Ps[(ii*16+ty)*65 + j];
                #pragma unroll
                for (int ee=0;ee<8;ee++) rv[ee] = Vs[j*132 + ee*16+tx];
                #pragma unroll
                for (int ii=0;ii<8;ii++)
                    #pragma unroll
                    for (int ee=0;ee<8;ee++) acc[ii][ee] += rp[ii]*rv[ee];
            }
        }
        __syncthreads();
    }

    float linv[8];
    #pragma unroll
    for (int ii=0;ii<8;ii++) linv[ii] = 1.f/lrow[ii*16+ty];
    #pragma unroll
    for (int ii=0;ii<8;ii++){
        int i = ii*16+ty;
        #pragma unroll
        for (int ee=0;ee<8;ee++)
            g_att[base + (size_t)(qb*128+i)*DD + ee*16+tx] = acc[ii][ee]*linv[ii];
    }
}

// ---------------- M update partials: split-K over (b,s), + z column sums ----------------
__global__ __launch_bounds__(256) void m_update_kernel()
{
    __shared__ float As[16][132];
    __shared__ float Bs[16][132];
    int h = blockIdx.x, c = blockIdx.y;       // head, k-chunk (256 rows)
    int b = c>>3, s0 = (c&7)*256;
    size_t base = (((size_t)(b*HH + h))*SS + s0)*DD;
    int t = threadIdx.x, ty=t>>4, tx=t&15;
    float acc[8][8];
    #pragma unroll
    for (int i=0;i<8;i++)
        #pragma unroll
        for (int j=0;j<8;j++) acc[i][j]=0.f;
    float zacc = 0.f;

    for (int k0=0;k0<256;k0+=16){
        #pragma unroll
        for (int i=0;i<2;i++){
            int idx = t + i*256; int r = idx>>5, c4 = idx&31;
            *(float4*)(&As[r][c4*4]) = *(const float4*)(g_sk + base + (size_t)(k0+r)*DD + c4*4);
            *(float4*)(&Bs[r][c4*4]) = *(const float4*)(g_v  + base + (size_t)(k0+r)*DD + c4*4);
        }
        __syncthreads();
        if (t < 128){
            #pragma unroll
            for (int kk=0;kk<16;kk++) zacc += As[kk][t];
        }
        #pragma unroll
        for (int kk=0;kk<16;kk++){
            float ra[8], rb[8];
            #pragma unroll
            for (int i=0;i<8;i++) ra[i] = As[kk][i*16+ty];
            #pragma unroll
            for (int j=0;j<8;j++) rb[j] = Bs[kk][j*16+tx];
            #pragma unroll
            for (int i=0;i<8;i++)
                #pragma unroll
                for (int j=0;j<8;j++) acc[i][j] += ra[i]*rb[j];
        }
        __syncthreads();
    }
    size_t pbase = ((size_t)(h*16 + c)) << 14;  // *128*128
    #pragma unroll
    for (int i=0;i<8;i++)
        #pragma unroll
        for (int j=0;j<8;j++)
            g_mpart[pbase + (size_t)(i*16+ty)*DD + j*16+tx] = acc[i][j];
    if (t < 128) g_zpart[(h*16 + c)*DD + t] = zacc;
}

__global__ void reduce_m_kernel(const float* __restrict__ M, float* __restrict__ out)
{
    int idx = blockIdx.x*256 + threadIdx.x;    // 262144 total
    int h = idx >> 14;
    int de = idx & 16383;
    float s = M[idx];
    #pragma unroll
    for (int c=0;c<16;c++) s += g_mpart[(((size_t)(h*16+c))<<14) + de];
    out[idx] = s;
}

__global__ void reduce_z_kernel(const float* __restrict__ z, float* __restrict__ out)
{
    int idx = blockIdx.x*256 + threadIdx.x;    // 2048 total
    float s = z[idx];
    int h = idx >> 7, d = idx & 127;
    #pragma unroll
    for (int c=0;c<16;c++) s += g_zpart[(h*16+c)*DD + d];
    out[idx] = s;
}

// ---------------- output projection with fused gated combine ----------------
__global__ __launch_bounds__(256) void gemm_out_kernel(
    const float* __restrict__ Wo, const float* __restrict__ beta, float* __restrict__ out)
{
    __shared__ float As[128][20];
    __shared__ float Bs[16][132];
    int m0 = blockIdx.y*128, n0 = blockIdx.x*128;
    int t = threadIdx.x, ty=t>>4, tx=t&15;
    float g = 1.f/(1.f + expf(-beta[0]));
    float gc = 1.f - g;
    float acc[8][8];
    #pragma unroll
    for (int i=0;i<8;i++)
        #pragma unroll
        for (int j=0;j<8;j++) acc[i][j]=0.f;

    for (int k0=0;k0<HIDN;k0+=16){
        #pragma unroll
        for (int i=0;i<2;i++){
            int idx = t + i*256;
            int r = idx>>2, c4 = idx&3;
            int m = m0 + r;
            int b = m>>11, s = m&2047;
            int k = k0 + c4*4;
            int h = k>>7, d = k&127;
            size_t a = (((size_t)(b*HH+h))*SS + s)*DD + d;
            float4 mm = *(const float4*)(g_mem + a);
            float4 aa = *(const float4*)(g_att + a);
            float4 v;
            v.x = g*mm.x + gc*aa.x;
            v.y = g*mm.y + gc*aa.y;
            v.z = g*mm.z + gc*aa.z;
            v.w = g*mm.w + gc*aa.w;
            *(float4*)(&As[r][c4*4]) = v;
            int r2 = idx>>5, c42 = idx&31;
            *(float4*)(&Bs[r2][c42*4]) = *(const float4*)(Wo + (size_t)(k0+r2)*HIDN + n0 + c42*4);
        }
        __syncthreads();
        #pragma unroll
        for (int kk=0;kk<16;kk++){
            float ra[8], rb[8];
            #pragma unroll
            for (int i=0;i<8;i++) ra[i] = As[i*16+ty][kk];
            #pragma unroll
            for (int j=0;j<8;j++) rb[j] = Bs[kk][j*16+tx];
            #pragma unroll
            for (int i=0;i<8;i++)
                #pragma unroll
                for (int j=0;j<8;j++) acc[i][j] += ra[i]*rb[j];
        }
        __syncthreads();
    }
    #pragma unroll
    for (int i=0;i<8;i++){
        int m = m0 + i*16+ty;
        #pragma unroll
        for (int j=0;j<8;j++)
            out[(size_t)m*HIDN + n0 + j*16+tx] = acc[i][j];
    }
}

// ---------------- launch ----------------
extern "C" void kernel_launch(void* const* d_in, const int* in_sizes, int n_in,
                              void* d_out, int out_size)
{
    (void)in_sizes; (void)n_in; (void)out_size;
    const float* hs   = (const float*)d_in[0];
    const float* Wq   = (const float*)d_in[1];
    const float* bq   = (const float*)d_in[2];
    const float* Wk   = (const float*)d_in[3];
    const float* bk   = (const float*)d_in[4];
    const float* Wv   = (const float*)d_in[5];
    const float* bv   = (const float*)d_in[6];
    const float* Wo   = (const float*)d_in[7];
    const float* beta = (const float*)d_in[8];
    const float* Mm   = (const float*)d_in[9];
    const float* zz   = (const float*)d_in[10];
    // d_in[11] = attention_mask (pure causal by construction; applied analytically)
    const int* pos    = (const int*)d_in[12];
    float* out = (float*)d_out;

    dim3 gq(16, 32, 3);
    gemm_qkv_kernel<<<gq, 256>>>(hs, Wq, Wk, Wv, bq, bk, bv);

    rope_kernel<<<BHS/2, 256>>>(pos);

    int mem_smem = (128*132*2 + 128) * 4;
    cudaFuncSetAttribute(memret_kernel, cudaFuncAttributeMaxDynamicSharedMemorySize, mem_smem);
    memret_kernel<<<dim3(16,32), 256, mem_smem>>>(Mm, zz);

    int fl_smem = (128*132 + 128*64 + 64*132 + 128*65 + 3*128) * 4;
    cudaFuncSetAttribute(attn_flash_kernel, cudaFuncAttributeMaxDynamicSharedMemorySize, fl_smem);
    attn_flash_kernel<<<dim3(16,32), 256, fl_smem>>>();

    m_update_kernel<<<dim3(16,16), 256>>>();

    reduce_m_kernel<<<1024, 256>>>(Mm, out + 8388608);
    reduce_z_kernel<<<8, 256>>>(zz, out + 8388608 + 262144);

    gemm_out_kernel<<<dim3(16,32), 256>>>(Wo, beta, out);
}

// round 7
// speedup vs baseline: 1.7560x; 1.7560x over previous
#include <cuda_runtime.h>
#include <cuda_bf16.h>
#include <math.h>
#include <stdint.h>

#define BB 2
#define SS 2048
#define HH 16
#define DD 128
#define HIDN 2048
#define BHS (BB*HH*SS)          // 65536 rows of length D
#define MTOT 4096               // B*S rows

// ---------------- scratch (static device globals; no allocation) ----------------
__device__ float g_q  [BB*HH*SS*DD];
__device__ float g_k  [BB*HH*SS*DD];
__device__ float g_v  [BB*HH*SS*DD];
__device__ float g_sq [BB*HH*SS*DD];
__device__ float g_sk [BB*HH*SS*DD];
__device__ float g_mem[BB*HH*SS*DD];
__device__ float g_att[BB*HH*SS*DD];
__device__ float g_mpart[HH*16*DD*DD];
__device__ float g_zpart[HH*16*DD];

// bf16 split-precision operands
__device__ __nv_bfloat16 g_AH[MTOT*HIDN];
__device__ __nv_bfloat16 g_AL[MTOT*HIDN];
__device__ __nv_bfloat16 g_WtH[4u*HIDN*HIDN];   // [which][n][k] transposed
__device__ __nv_bfloat16 g_WtL[4u*HIDN*HIDN];
__device__ __nv_bfloat16 g_CH[MTOT*HIDN];       // gated combine, split
__device__ __nv_bfloat16 g_CL[MTOT*HIDN];

// ================= mma.sync helpers (sm_80+ PTX; valid on plain sm_103 target) =================
__device__ __forceinline__ uint32_t smem_u32(const void* p){
    return (uint32_t)__cvta_generic_to_shared(p);
}

__device__ __forceinline__ void ldsm_x4(uint32_t& r0, uint32_t& r1, uint32_t& r2, uint32_t& r3, uint32_t addr){
    asm volatile("ldmatrix.sync.aligned.m8n8.x4.shared.b16 {%0,%1,%2,%3}, [%4];"
        : "=r"(r0), "=r"(r1), "=r"(r2), "=r"(r3) : "r"(addr));
}
__device__ __forceinline__ void ldsm_x2(uint32_t& r0, uint32_t& r1, uint32_t addr){
    asm volatile("ldmatrix.sync.aligned.m8n8.x2.shared.b16 {%0,%1}, [%2];"
        : "=r"(r0), "=r"(r1) : "r"(addr));
}
__device__ __forceinline__ void mma_bf16(float* d, const uint32_t* a, const uint32_t* b){
    asm volatile("mma.sync.aligned.m16n8k16.row.col.f32.bf16.bf16.f32 "
        "{%0,%1,%2,%3}, {%4,%5,%6,%7}, {%8,%9}, {%0,%1,%2,%3};"
        : "+f"(d[0]), "+f"(d[1]), "+f"(d[2]), "+f"(d[3])
        : "r"(a[0]), "r"(a[1]), "r"(a[2]), "r"(a[3]), "r"(b[0]), "r"(b[1]));
}

// ================= pre-pass kernels =================
__global__ __launch_bounds__(256) void split_a_kernel(const float* __restrict__ A)
{
    int idx = blockIdx.x*256 + threadIdx.x;
    float a = A[idx];
    __nv_bfloat16 h = __float2bfloat16_rn(a);
    g_AH[idx] = h;
    g_AL[idx] = __float2bfloat16_rn(a - __bfloat162float(h));
}

__global__ __launch_bounds__(256) void wsplit_kernel(
    const float* __restrict__ Wq, const float* __restrict__ Wk,
    const float* __restrict__ Wv, const float* __restrict__ Wo)
{
    __shared__ float tile[32][33];
    int z = blockIdx.z;
    const float* W = (z==0)?Wq:((z==1)?Wk:((z==2)?Wv:Wo));
    __nv_bfloat16* H = g_WtH + (size_t)z*HIDN*HIDN;
    __nv_bfloat16* L = g_WtL + (size_t)z*HIDN*HIDN;
    int n0 = blockIdx.x*32, k0 = blockIdx.y*32;
    int tx = threadIdx.x & 31, ty = threadIdx.x >> 5;
    #pragma unroll
    for (int i=0;i<4;i++)
        tile[ty+8*i][tx] = W[(size_t)(k0+ty+8*i)*HIDN + n0+tx];
    __syncthreads();
    #pragma unroll
    for (int i=0;i<4;i++){
        float v = tile[tx][ty+8*i];
        __nv_bfloat16 h = __float2bfloat16_rn(v);
        size_t o = (size_t)(n0+ty+8*i)*HIDN + k0+tx;
        H[o] = h;
        L[o] = __float2bfloat16_rn(v - __bfloat162float(h));
    }
}

__global__ __launch_bounds__(256) void combine_split_kernel(const float* __restrict__ beta)
{
    int idx = blockIdx.x*256 + threadIdx.x;
    float g = 1.f/(1.f + expf(-beta[0]));
    int m = idx >> 11, kcol = idx & 2047;
    int b = m>>11, s = m&2047, h = kcol>>7, d = kcol&127;
    size_t a = (((size_t)(b*HH+h))*SS + s)*DD + d;
    float v = g*g_mem[a] + (1.f-g)*g_att[a];
    __nv_bfloat16 hh = __float2bfloat16_rn(v);
    g_CH[idx] = hh;
    g_CL[idx] = __float2bfloat16_rn(v - __bfloat162float(hh));
}

// ================= HMMA GEMM: C[128m x 128n] per CTA, K=2048, split precision =================
// smem: 4 tiles (Ah, Al, Bh, Bl), each 128 rows x 32 bf16, padded row stride 40 bf16 (80B).
#define TSTRIDE 40
#define TILE_BF16 (128*TSTRIDE)              // 5120 bf16 per tile
#define TILE_U4   (TILE_BF16/8)              // 640 uint4 per tile

// asel: 0 -> A = g_AH/g_AL (QKV, mode 0, which = blockIdx.z)
//       1 -> A = g_CH/g_CL (out-proj, mode 1, which = 3)
__global__ __launch_bounds__(256) void gemm_mma_kernel(
    const float* __restrict__ bq, const float* __restrict__ bk, const float* __restrict__ bv,
    float* __restrict__ outp, int asel)
{
    __shared__ __nv_bfloat16 smem[4*TILE_BF16];   // 40KB
    uint32_t sbase = smem_u32(smem);
    uint4* s4 = (uint4*)smem;

    int t = threadIdx.x;
    int wid = t>>5, lane = t&31;
    int wm = wid>>2, wn = wid&3;           // warp 64m x 32n tile
    int n0 = blockIdx.x*128;
    int m0 = blockIdx.y*128;
    int which = (asel==0) ? blockIdx.z : 3;
    const __nv_bfloat16* Ah = (asel==0) ? g_AH : g_CH;   // device-side symbol refs (the round-5 bug fix)
    const __nv_bfloat16* Al = (asel==0) ? g_AL : g_CL;
    const __nv_bfloat16* Bh = g_WtH + (size_t)which*HIDN*HIDN;
    const __nv_bfloat16* Bl = g_WtL + (size_t)which*HIDN*HIDN;

    const __nv_bfloat16* gsrc[4] = {
        Ah + (size_t)m0*HIDN, Al + (size_t)m0*HIDN,
        Bh + (size_t)n0*HIDN, Bl + (size_t)n0*HIDN };

    // per-thread load slots: 8 x uint4 (2048 uint4 total per K-slab)
    int tt[8], rr[8], cc[8];
    #pragma unroll
    for (int i=0;i<8;i++){
        int slot = t + i*256;
        tt[i] = slot>>9;
        int w = slot&511;
        rr[i] = w>>2;
        cc[i] = w&3;
    }

    float acc[4][4][4];
    #pragma unroll
    for (int mt=0;mt<4;mt++)
        #pragma unroll
        for (int nt=0;nt<4;nt++)
            #pragma unroll
            for (int e=0;e<4;e++) acc[mt][nt][e] = 0.f;

    uint32_t aRow = (uint32_t)(wm*64 + (lane&15));
    uint32_t aChk = (uint32_t)(lane>>4);
    uint32_t bRow = (uint32_t)(wn*32 + (lane&7));
    uint32_t bChk = (uint32_t)((lane>>3)&1);

    uint4 buf[8];
    #pragma unroll
    for (int i=0;i<8;i++)
        buf[i] = *(const uint4*)(gsrc[tt[i]] + (size_t)rr[i]*HIDN + cc[i]*8);

    for (int kt=0; kt<64; kt++){
        // store prefetched slab
        #pragma unroll
        for (int i=0;i<8;i++)
            s4[tt[i]*TILE_U4 + rr[i]*5 + cc[i]] = buf[i];
        __syncthreads();
        // prefetch next slab (LDGs in flight during compute)
        if (kt < 63){
            int k0 = (kt+1)*32;
            #pragma unroll
            for (int i=0;i<8;i++)
                buf[i] = *(const uint4*)(gsrc[tt[i]] + (size_t)rr[i]*HIDN + k0 + cc[i]*8);
        }

        #pragma unroll
        for (int k16=0;k16<2;k16++){
            uint32_t aH[4][4], aL[4][4], bH[4][2], bL[4][2];
            #pragma unroll
            for (int mt=0;mt<4;mt++){
                uint32_t off = (aRow + mt*16)*80u + (k16*2 + aChk)*16u;
                ldsm_x4(aH[mt][0],aH[mt][1],aH[mt][2],aH[mt][3], sbase + 0*TILE_BF16*2 + off);
                ldsm_x4(aL[mt][0],aL[mt][1],aL[mt][2],aL[mt][3], sbase + 1*TILE_BF16*2 + off);
            }
            #pragma unroll
            for (int nt=0;nt<4;nt++){
                uint32_t off = (bRow + nt*8)*80u + (k16*2 + bChk)*16u;
                ldsm_x2(bH[nt][0],bH[nt][1], sbase + 2*TILE_BF16*2 + off);
                ldsm_x2(bL[nt][0],bL[nt][1], sbase + 3*TILE_BF16*2 + off);
            }
            #pragma unroll
            for (int mt=0;mt<4;mt++)
                #pragma unroll
                for (int nt=0;nt<4;nt++){
                    mma_bf16(acc[mt][nt], aH[mt], bH[nt]);
                    mma_bf16(acc[mt][nt], aH[mt], bL[nt]);
                    mma_bf16(acc[mt][nt], aL[mt], bH[nt]);
                }
        }
        __syncthreads();
    }

    // epilogue: fragment layout d0:(r,c) d1:(r,c+1) d2:(r+8,c) d3:(r+8,c+1)
    int rB = wm*64 + (lane>>2);
    int cB = wn*32 + (lane&3)*2;
    if (asel == 0){
        const float* bias = (which==0)?bq:((which==1)?bk:bv);
        float* O = (which==0)?g_q:((which==1)?g_k:g_v);
        int h = n0>>7;   // BN=128 aligns with head dim
        #pragma unroll
        for (int mt=0;mt<4;mt++){
            #pragma unroll
            for (int nt=0;nt<4;nt++){
                int row = rB + mt*16;
                int col = cB + nt*8;          // d index within head
                int n = n0 + col;
                #pragma unroll
                for (int half=0; half<2; half++){
                    int m = m0 + row + half*8;
                    int b = m>>11, s = m&2047;
                    size_t o = (((size_t)(b*HH+h))*SS + s)*DD + col;
                    O[o]   = acc[mt][nt][half*2+0] + bias[n];
                    O[o+1] = acc[mt][nt][half*2+1] + bias[n+1];
                }
            }
        }
    } else {
        #pragma unroll
        for (int mt=0;mt<4;mt++){
            #pragma unroll
            for (int nt=0;nt<4;nt++){
                int row = rB + mt*16;
                int col = cB + nt*8;
                #pragma unroll
                for (int half=0; half<2; half++){
                    size_t o = (size_t)(m0 + row + half*8)*HIDN + n0 + col;
                    outp[o]   = acc[mt][nt][half*2+0];
                    outp[o+1] = acc[mt][nt][half*2+1];
                }
            }
        }
    }
}

// ---------------- RoPE + sigma(elu+1); in-place q/k, writes sig_q/sig_k ----------------
__global__ __launch_bounds__(256) void rope_kernel(const int* __restrict__ pos)
{
    int t = threadIdx.x;
    long rid = (long)blockIdx.x*2 + (t>>7);   // row over (b,h,s)
    int d = t & 127;
    int s  = (int)(rid & (SS-1));
    int bh = (int)(rid >> 11);
    int b  = bh >> 4;
    size_t base = (size_t)rid * DD;
    float qv = g_q[base+d], kv = g_k[base+d];
    float qo = (d<64)? -g_q[base+d+64] : g_q[base+d-64];
    float ko = (d<64)? -g_k[base+d+64] : g_k[base+d-64];
    int p = pos[(size_t)b*SS + s];
    float inv = expf(-0.14391156831212787f * (float)(d & 63));
    float ang = (float)p * inv;
    float sn, cs;
    sincosf(ang, &sn, &cs);
    float qn = qv*cs + qo*sn;
    float kn = kv*cs + ko*sn;
    __syncthreads();
    g_q[base+d] = qn;
    g_k[base+d] = kn;
    g_sq[base+d] = (qn>0.f) ? qn+1.f : expf(qn);
    g_sk[base+d] = (kn>0.f) ? kn+1.f : expf(kn);
}

// ---------------- memory retrieval: (sig_q @ M[h]) / (sig_q . z[h]) ----------------
__global__ __launch_bounds__(256) void memret_kernel(
    const float* __restrict__ M, const float* __restrict__ z)
{
    extern __shared__ float sm[];
    float* Sq = sm;
    float* Ms = Sq + 128*132;
    float* zs = Ms + 128*132;
    int s0 = blockIdx.x * 128;
    int bh = blockIdx.y;
    int h  = bh & 15;
    int t = threadIdx.x, ty=t>>4, tx=t&15;
    size_t base = (size_t)bh*SS*DD + (size_t)s0*DD;
    #pragma unroll
    for (int i=0;i<16;i++){
        int idx = t + i*256; int r = idx>>5, c4 = idx&31;
        *(float4*)(&Sq[r*132 + c4*4]) = *(const float4*)(g_sq + base + (size_t)r*DD + c4*4);
        *(float4*)(&Ms[r*132 + c4*4]) = *(const float4*)(M + (size_t)h*DD*DD + (size_t)r*DD + c4*4);
    }
    if (t < 128) zs[t] = z[h*DD + t];
    __syncthreads();

    float acc[8][8], den[8];
    #pragma unroll
    for (int i=0;i<8;i++){
        den[i]=0.f;
        #pragma unroll
        for (int j=0;j<8;j++) acc[i][j]=0.f;
    }
    for (int d=0; d<128; d++){
        float zv = zs[d];
        float rq[8], rm[8];
        #pragma unroll
        for (int i=0;i<8;i++) rq[i] = Sq[(i*16+ty)*132 + d];
        #pragma unroll
        for (int j=0;j<8;j++) rm[j] = Ms[d*132 + j*16+tx];
        #pragma unroll
        for (int i=0;i<8;i++){
            den[i] += rq[i]*zv;
            #pragma unroll
            for (int j=0;j<8;j++) acc[i][j] += rq[i]*rm[j];
        }
    }
    #pragma unroll
    for (int i=0;i<8;i++){
        float dinv = 1.f/den[i];
        #pragma unroll
        for (int j=0;j<8;j++)
            g_mem[base + (size_t)(i*16+ty)*DD + j*16+tx] = acc[i][j]*dinv;
    }
}

// ---------------- causal flash attention (fp32) ----------------
__global__ __launch_bounds__(256) void attn_flash_kernel()
{
    extern __shared__ float sm[];
    float* Qs  = sm;
    float* Ks  = Qs + 128*132;
    float* Vs  = Ks + 128*64;
    float* Ps  = Vs + 64*132;
    float* mrow= Ps + 128*65;
    float* lrow= mrow + 128;
    float* rs  = lrow + 128;
    int qb = blockIdx.x;
    int bh = blockIdx.y;
    int t = threadIdx.x, ty = t>>4, tx = t&15;
    size_t base = (size_t)bh * SS * DD;

    #pragma unroll
    for (int i=0;i<16;i++){
        int idx = t + i*256; int r = idx>>5, c4 = idx&31;
        *(float4*)(&Qs[r*132 + c4*4]) =
            *(const float4*)(g_q + base + (size_t)(qb*128 + r)*DD + c4*4);
    }
    if (t < 128){ mrow[t] = -INFINITY; lrow[t] = 0.f; }
    float acc[8][8];
    #pragma unroll
    for (int i=0;i<8;i++)
        #pragma unroll
        for (int j=0;j<8;j++) acc[i][j]=0.f;
    __syncthreads();

    const float sscale = 0.08838834764831845f;
    int jbmax = 2*qb + 1;
    for (int jb=0;jb<=jbmax;jb++){
        #pragma unroll
        for (int i=0;i<8;i++){
            int idx = t + i*256; int r = idx>>5, c4 = idx&31;
            size_t g = base + (size_t)(jb*64 + r)*DD + c4*4;
            float4 kk4 = *(const float4*)(g_k + g);
            int sw = r ^ c4;
            Ks[(4*c4+0)*64 + sw] = kk4.x;
            Ks[(4*c4+1)*64 + sw] = kk4.y;
            Ks[(4*c4+2)*64 + sw] = kk4.z;
            Ks[(4*c4+3)*64 + sw] = kk4.w;
            *(float4*)(&Vs[r*132 + c4*4]) = *(const float4*)(g_v + g);
        }
        __syncthreads();

        float sacc[8][4];
        #pragma unroll
        for (int i=0;i<8;i++)
            #pragma unroll
            for (int j=0;j<4;j++) sacc[i][j]=0.f;
        for (int d=0; d<128; d++){
            float rq[8], rk[4];
            int c = d>>2;
            #pragma unroll
            for (int ii=0;ii<8;ii++) rq[ii] = Qs[(ii*16+ty)*132 + d];
            #pragma unroll
            for (int jj=0;jj<4;jj++) rk[jj] = Ks[d*64 + ((jj*16+tx)^c)];
            #pragma unroll
            for (int ii=0;ii<8;ii++)
                #pragma unroll
                for (int jj=0;jj<4;jj++) sacc[ii][jj] += rq[ii]*rk[jj];
        }
        #pragma unroll
        for (int ii=0;ii<8;ii++){
            int i = ii*16+ty;
            int qrow = qb*128 + i;
            #pragma unroll
            for (int jj=0;jj<4;jj++){
                int j = jj*16+tx;
                int kcol = jb*64 + j;
                Ps[i*65 + j] = (kcol <= qrow) ? sacc[ii][jj]*sscale : -INFINITY;
            }
        }
        __syncthreads();

        if (t < 128){
            float m_old = mrow[t], l_old = lrow[t];
            float tmax = -INFINITY;
            #pragma unroll 8
            for (int j=0;j<64;j++) tmax = fmaxf(tmax, Ps[t*65+j]);
            float m_new = fmaxf(m_old, tmax);
            float sc = __expf(m_old - m_new);
            float sum = 0.f;
            #pragma unroll 8
            for (int j=0;j<64;j++){
                float p = __expf(Ps[t*65+j] - m_new);
                Ps[t*65+j] = p;
                sum += p;
            }
            mrow[t] = m_new;
            lrow[t] = sc*l_old + sum;
            rs[t]   = sc;
        }
        __syncthreads();

        {
            float scl[8];
            #pragma unroll
            for (int ii=0;ii<8;ii++) scl[ii] = rs[ii*16+ty];
            #pragma unroll
            for (int ii=0;ii<8;ii++)
                #pragma unroll
                for (int ee=0;ee<8;ee++) acc[ii][ee] *= scl[ii];
            for (int j=0;j<64;j++){
                float rp[8], rv[8];
                #pragma unroll
                for (int ii=0;ii<8;ii++) rp[ii] = Ps[(ii*16+ty)*65 + j];
                #pragma unroll
                for (int ee=0;ee<8;ee++) rv[ee] = Vs[j*132 + ee*16+tx];
                #pragma unroll
                for (int ii=0;ii<8;ii++)
                    #pragma unroll
                    for (int ee=0;ee<8;ee++) acc[ii][ee] += rp[ii]*rv[ee];
            }
        }
        __syncthreads();
    }

    float linv[8];
    #pragma unroll
    for (int ii=0;ii<8;ii++) linv[ii] = 1.f/lrow[ii*16+ty];
    #pragma unroll
    for (int ii=0;ii<8;ii++){
        int i = ii*16+ty;
        #pragma unroll
        for (int ee=0;ee<8;ee++)
            g_att[base + (size_t)(qb*128+i)*DD + ee*16+tx] = acc[ii][ee]*linv[ii];
    }
}

// ---------------- M update partials: split-K over (b,s), + z column sums ----------------
__global__ __launch_bounds__(256) void m_update_kernel()
{
    __shared__ float As[16][132];
    __shared__ float Bs[16][132];
    int h = blockIdx.x, c = blockIdx.y;
    int b = c>>3, s0 = (c&7)*256;
    size_t base = (((size_t)(b*HH + h))*SS + s0)*DD;
    int t = threadIdx.x, ty=t>>4, tx=t&15;
    float acc[8][8];
    #pragma unroll
    for (int i=0;i<8;i++)
        #pragma unroll
        for (int j=0;j<8;j++) acc[i][j]=0.f;
    float zacc = 0.f;

    for (int k0=0;k0<256;k0+=16){
        #pragma unroll
        for (int i=0;i<2;i++){
            int idx = t + i*256; int r = idx>>5, c4 = idx&31;
            *(float4*)(&As[r][c4*4]) = *(const float4*)(g_sk + base + (size_t)(k0+r)*DD + c4*4);
            *(float4*)(&Bs[r][c4*4]) = *(const float4*)(g_v  + base + (size_t)(k0+r)*DD + c4*4);
        }
        __syncthreads();
        if (t < 128){
            #pragma unroll
            for (int kk=0;kk<16;kk++) zacc += As[kk][t];
        }
        #pragma unroll
        for (int kk=0;kk<16;kk++){
            float ra[8], rb[8];
            #pragma unroll
            for (int i=0;i<8;i++) ra[i] = As[kk][i*16+ty];
            #pragma unroll
            for (int j=0;j<8;j++) rb[j] = Bs[kk][j*16+tx];
            #pragma unroll
            for (int i=0;i<8;i++)
                #pragma unroll
                for (int j=0;j<8;j++) acc[i][j] += ra[i]*rb[j];
        }
        __syncthreads();
    }
    size_t pbase = ((size_t)(h*16 + c)) << 14;
    #pragma unroll
    for (int i=0;i<8;i++)
        #pragma unroll
        for (int j=0;j<8;j++)
            g_mpart[pbase + (size_t)(i*16+ty)*DD + j*16+tx] = acc[i][j];
    if (t < 128) g_zpart[(h*16 + c)*DD + t] = zacc;
}

__global__ void reduce_m_kernel(const float* __restrict__ M, float* __restrict__ out)
{
    int idx = blockIdx.x*256 + threadIdx.x;
    int h = idx >> 14;
    int de = idx & 16383;
    float s = M[idx];
    #pragma unroll
    for (int c=0;c<16;c++) s += g_mpart[(((size_t)(h*16+c))<<14) + de];
    out[idx] = s;
}

__global__ void reduce_z_kernel(const float* __restrict__ z, float* __restrict__ out)
{
    int idx = blockIdx.x*256 + threadIdx.x;
    float s = z[idx];
    int h = idx >> 7, d = idx & 127;
    #pragma unroll
    for (int c=0;c<16;c++) s += g_zpart[(h*16+c)*DD + d];
    out[idx] = s;
}

// ---------------- launch ----------------
extern "C" void kernel_launch(void* const* d_in, const int* in_sizes, int n_in,
                              void* d_out, int out_size)
{
    (void)in_sizes; (void)n_in; (void)out_size;
    const float* hs   = (const float*)d_in[0];
    const float* Wq   = (const float*)d_in[1];
    const float* bq   = (const float*)d_in[2];
    const float* Wk   = (const float*)d_in[3];
    const float* bk   = (const float*)d_in[4];
    const float* Wv   = (const float*)d_in[5];
    const float* bv   = (const float*)d_in[6];
    const float* Wo   = (const float*)d_in[7];
    const float* beta = (const float*)d_in[8];
    const float* Mm   = (const float*)d_in[9];
    const float* zz   = (const float*)d_in[10];
    const int* pos    = (const int*)d_in[12];
    float* out = (float*)d_out;

    int mem_smem = (128*132*2 + 128) * 4;
    cudaFuncSetAttribute(memret_kernel, cudaFuncAttributeMaxDynamicSharedMemorySize, mem_smem);
    int fl_smem = (128*132 + 128*64 + 64*132 + 128*65 + 3*128) * 4;
    cudaFuncSetAttribute(attn_flash_kernel, cudaFuncAttributeMaxDynamicSharedMemorySize, fl_smem);

    // split A (hidden) + split/transpose weights
    split_a_kernel<<<MTOT*HIDN/256, 256>>>(hs);
    wsplit_kernel<<<dim3(64,64,4), 256>>>(Wq, Wk, Wv, Wo);

    // QKV via HMMA (3-pass split precision); A selected device-side (asel=0)
    gemm_mma_kernel<<<dim3(16,32,3), 256>>>(bq, bk, bv, nullptr, 0);

    rope_kernel<<<BHS/2, 256>>>(pos);

    memret_kernel<<<dim3(16,32), 256, mem_smem>>>(Mm, zz);

    attn_flash_kernel<<<dim3(16,32), 256, fl_smem>>>();

    m_update_kernel<<<dim3(16,16), 256>>>();
    reduce_m_kernel<<<1024, 256>>>(Mm, out + 8388608);
    reduce_z_kernel<<<8, 256>>>(zz, out + 8388608 + 262144);

    // gated combine + split, then output projection via HMMA (asel=1)
    combine_split_kernel<<<MTOT*HIDN/256, 256>>>(beta);
    gemm_mma_kernel<<<dim3(16,32,1), 256>>>(bq, bk, bv, out, 1);
}

// round 11
// speedup vs baseline: 2.5456x; 1.4497x over previous
#include <cuda_runtime.h>
#include <cuda_bf16.h>
#include <math.h>
#include <stdint.h>

#define BB 2
#define SS 2048
#define HH 16
#define DD 128
#define HIDN 2048
#define BHS (BB*HH*SS)          // 65536 rows of length D
#define MTOT 4096               // B*S rows

// ---------------- scratch (static device globals; no allocation) ----------------
__device__ float g_v  [BB*HH*SS*DD];
__device__ float g_sq [BB*HH*SS*DD];
__device__ float g_sk [BB*HH*SS*DD];
__device__ float g_mem[BB*HH*SS*DD];
__device__ float g_att[BB*HH*SS*DD];
__device__ float g_den[BHS];
__device__ float g_mpart[HH*16*DD*DD];
__device__ float g_zpart[HH*16*DD];

// bf16 split-precision operands
__device__ __nv_bfloat16 g_AH[MTOT*HIDN];
__device__ __nv_bfloat16 g_AL[MTOT*HIDN];
__device__ __nv_bfloat16 g_WtH[4u*HIDN*HIDN];   // [which][n][k] transposed
__device__ __nv_bfloat16 g_WtL[4u*HIDN*HIDN];
__device__ __nv_bfloat16 g_CH[MTOT*HIDN];       // gated combine, split
__device__ __nv_bfloat16 g_CL[MTOT*HIDN];
__device__ __nv_bfloat16 g_qH[BB*HH*SS*DD];     // post-rope q/k splits
__device__ __nv_bfloat16 g_qL[BB*HH*SS*DD];
__device__ __nv_bfloat16 g_kH[BB*HH*SS*DD];
__device__ __nv_bfloat16 g_kL[BB*HH*SS*DD];
__device__ __nv_bfloat16 g_sqH[BB*HH*SS*DD];    // sigma(q) splits
__device__ __nv_bfloat16 g_sqL[BB*HH*SS*DD];
__device__ __nv_bfloat16 g_MtH[HH*DD*DD];       // M transposed [h][e][d] splits
__device__ __nv_bfloat16 g_MtL[HH*DD*DD];

// ================= mma.sync helpers (validated round 6) =================
__device__ __forceinline__ uint32_t smem_u32(const void* p){
    return (uint32_t)__cvta_generic_to_shared(p);
}
__device__ __forceinline__ void ldsm_x4(uint32_t& r0, uint32_t& r1, uint32_t& r2, uint32_t& r3, uint32_t addr){
    asm volatile("ldmatrix.sync.aligned.m8n8.x4.shared.b16 {%0,%1,%2,%3}, [%4];"
        : "=r"(r0), "=r"(r1), "=r"(r2), "=r"(r3) : "r"(addr));
}
__device__ __forceinline__ void ldsm_x2(uint32_t& r0, uint32_t& r1, uint32_t addr){
    asm volatile("ldmatrix.sync.aligned.m8n8.x2.shared.b16 {%0,%1}, [%2];"
        : "=r"(r0), "=r"(r1) : "r"(addr));
}
__device__ __forceinline__ void mma_bf16(float* d, const uint32_t* a, const uint32_t* b){
    asm volatile("mma.sync.aligned.m16n8k16.row.col.f32.bf16.bf16.f32 "
        "{%0,%1,%2,%3}, {%4,%5,%6,%7}, {%8,%9}, {%0,%1,%2,%3};"
        : "+f"(d[0]), "+f"(d[1]), "+f"(d[2]), "+f"(d[3])
        : "r"(a[0]), "r"(a[1]), "r"(a[2]), "r"(a[3]), "r"(b[0]), "r"(b[1]));
}
__device__ __forceinline__ void bf16split(float v, __nv_bfloat16& h, __nv_bfloat16& l){
    h = __float2bfloat16_rn(v);
    l = __float2bfloat16_rn(v - __bfloat162float(h));
}

// ================= pre-pass kernels =================
__global__ __launch_bounds__(256) void split_a_kernel(const float* __restrict__ A)
{
    int idx = blockIdx.x*256 + threadIdx.x;
    __nv_bfloat16 h,l; bf16split(A[idx], h, l);
    g_AH[idx] = h; g_AL[idx] = l;
}

__global__ __launch_bounds__(256) void wsplit_kernel(
    const float* __restrict__ Wq, const float* __restrict__ Wk,
    const float* __restrict__ Wv, const float* __restrict__ Wo)
{
    __shared__ float tile[32][33];
    int z = blockIdx.z;
    const float* W = (z==0)?Wq:((z==1)?Wk:((z==2)?Wv:Wo));
    __nv_bfloat16* H = g_WtH + (size_t)z*HIDN*HIDN;
    __nv_bfloat16* L = g_WtL + (size_t)z*HIDN*HIDN;
    int n0 = blockIdx.x*32, k0 = blockIdx.y*32;
    int tx = threadIdx.x & 31, ty = threadIdx.x >> 5;
    #pragma unroll
    for (int i=0;i<4;i++)
        tile[ty+8*i][tx] = W[(size_t)(k0+ty+8*i)*HIDN + n0+tx];
    __syncthreads();
    #pragma unroll
    for (int i=0;i<4;i++){
        __nv_bfloat16 h,l; bf16split(tile[tx][ty+8*i], h, l);
        size_t o = (size_t)(n0+ty+8*i)*HIDN + k0+tx;
        H[o] = h; L[o] = l;
    }
}

// transpose+split M: src [h][d][e] -> dst [h][e][d]
__global__ __launch_bounds__(256) void msplit_kernel(const float* __restrict__ M)
{
    int idx = blockIdx.x*256 + threadIdx.x;   // 262144
    int h = idx >> 14, d = (idx>>7)&127, e = idx&127;
    __nv_bfloat16 hh,ll; bf16split(M[idx], hh, ll);
    size_t o = (size_t)h*16384 + e*128 + d;
    g_MtH[o] = hh; g_MtL[o] = ll;
}

__global__ __launch_bounds__(256) void combine_split_kernel(const float* __restrict__ beta)
{
    int idx = blockIdx.x*256 + threadIdx.x;
    float g = 1.f/(1.f + expf(-beta[0]));
    int m = idx >> 11, kcol = idx & 2047;
    int b = m>>11, s = m&2047, h = kcol>>7, d = kcol&127;
    size_t a = (((size_t)(b*HH+h))*SS + s)*DD + d;
    float v = g*g_mem[a] + (1.f-g)*g_att[a];
    __nv_bfloat16 hh,ll; bf16split(v, hh, ll);
    g_CH[idx] = hh; g_CL[idx] = ll;
}

// ================= HMMA GEMM (validated round 6) =================
#define TSTRIDE 40
#define TILE_BF16 (128*TSTRIDE)
#define TILE_U4   (TILE_BF16/8)

__global__ __launch_bounds__(256) void gemm_mma_kernel(
    const float* __restrict__ bq, const float* __restrict__ bk, const float* __restrict__ bv,
    float* __restrict__ outp, int asel)
{
    __shared__ __nv_bfloat16 smem[4*TILE_BF16];
    uint32_t sbase = smem_u32(smem);
    uint4* s4 = (uint4*)smem;

    int t = threadIdx.x;
    int wid = t>>5, lane = t&31;
    int wm = wid>>2, wn = wid&3;
    int n0 = blockIdx.x*128;
    int m0 = blockIdx.y*128;
    int which = (asel==0) ? blockIdx.z : 3;
    const __nv_bfloat16* Ah = (asel==0) ? g_AH : g_CH;
    const __nv_bfloat16* Al = (asel==0) ? g_AL : g_CL;
    const __nv_bfloat16* Bh = g_WtH + (size_t)which*HIDN*HIDN;
    const __nv_bfloat16* Bl = g_WtL + (size_t)which*HIDN*HIDN;

    const __nv_bfloat16* gsrc[4] = {
        Ah + (size_t)m0*HIDN, Al + (size_t)m0*HIDN,
        Bh + (size_t)n0*HIDN, Bl + (size_t)n0*HIDN };

    int tt[8], rr[8], cc[8];
    #pragma unroll
    for (int i=0;i<8;i++){
        int slot = t + i*256;
        tt[i] = slot>>9;
        int w = slot&511;
        rr[i] = w>>2;
        cc[i] = w&3;
    }

    float acc[4][4][4];
    #pragma unroll
    for (int mt=0;mt<4;mt++)
        #pragma unroll
        for (int nt=0;nt<4;nt++)
            #pragma unroll
            for (int e=0;e<4;e++) acc[mt][nt][e] = 0.f;

    uint32_t aRow = (uint32_t)(wm*64 + (lane&15));
    uint32_t aChk = (uint32_t)(lane>>4);
    uint32_t bRow = (uint32_t)(wn*32 + (lane&7));
    uint32_t bChk = (uint32_t)((lane>>3)&1);

    uint4 buf[8];
    #pragma unroll
    for (int i=0;i<8;i++)
        buf[i] = *(const uint4*)(gsrc[tt[i]] + (size_t)rr[i]*HIDN + cc[i]*8);

    for (int kt=0; kt<64; kt++){
        #pragma unroll
        for (int i=0;i<8;i++)
            s4[tt[i]*TILE_U4 + rr[i]*5 + cc[i]] = buf[i];
        __syncthreads();
        if (kt < 63){
            int k0 = (kt+1)*32;
            #pragma unroll
            for (int i=0;i<8;i++)
                buf[i] = *(const uint4*)(gsrc[tt[i]] + (size_t)rr[i]*HIDN + k0 + cc[i]*8);
        }

        #pragma unroll
        for (int k16=0;k16<2;k16++){
            uint32_t aH[4][4], aL[4][4], bH[4][2], bL[4][2];
            #pragma unroll
            for (int mt=0;mt<4;mt++){
                uint32_t off = (aRow + mt*16)*80u + (k16*2 + aChk)*16u;
                ldsm_x4(aH[mt][0],aH[mt][1],aH[mt][2],aH[mt][3], sbase + 0*TILE_BF16*2 + off);
                ldsm_x4(aL[mt][0],aL[mt][1],aL[mt][2],aL[mt][3], sbase + 1*TILE_BF16*2 + off);
            }
            #pragma unroll
            for (int nt=0;nt<4;nt++){
                uint32_t off = (bRow + nt*8)*80u + (k16*2 + bChk)*16u;
                ldsm_x2(bH[nt][0],bH[nt][1], sbase + 2*TILE_BF16*2 + off);
                ldsm_x2(bL[nt][0],bL[nt][1], sbase + 3*TILE_BF16*2 + off);
            }
            #pragma unroll
            for (int mt=0;mt<4;mt++)
                #pragma unroll
                for (int nt=0;nt<4;nt++){
                    mma_bf16(acc[mt][nt], aH[mt], bH[nt]);
                    mma_bf16(acc[mt][nt], aH[mt], bL[nt]);
                    mma_bf16(acc[mt][nt], aL[mt], bH[nt]);
                }
        }
        __syncthreads();
    }

    int rB = wm*64 + (lane>>2);
    int cB = wn*32 + (lane&3)*2;
    if (asel == 0){
        const float* bias = (which==0)?bq:((which==1)?bk:bv);
        int h = n0>>7;
        #pragma unroll
        for (int mt=0;mt<4;mt++){
            #pragma unroll
            for (int nt=0;nt<4;nt++){
                int row = rB + mt*16;
                int col = cB + nt*8;
                int n = n0 + col;
                #pragma unroll
                for (int half=0; half<2; half++){
                    int m = m0 + row + half*8;
                    int b = m>>11, s = m&2047;
                    size_t o = (((size_t)(b*HH+h))*SS + s)*DD + col;
                    float v0 = acc[mt][nt][half*2+0] + bias[n];
                    float v1 = acc[mt][nt][half*2+1] + bias[n+1];
                    if (which == 2){            // V: fp32
                        g_v[o] = v0; g_v[o+1] = v1;
                    } else {                     // Q/K staging pre-rope
                        float* O = (which==0)?g_sq:g_sk;
                        O[o] = v0; O[o+1] = v1;
                    }
                }
            }
        }
    } else {
        #pragma unroll
        for (int mt=0;mt<4;mt++){
            #pragma unroll
            for (int nt=0;nt<4;nt++){
                int row = rB + mt*16;
                int col = cB + nt*8;
                #pragma unroll
                for (int half=0; half<2; half++){
                    size_t o = (size_t)(m0 + row + half*8)*HIDN + n0 + col;
                    outp[o]   = acc[mt][nt][half*2+0];
                    outp[o+1] = acc[mt][nt][half*2+1];
                }
            }
        }
    }
}

// ---------------- RoPE + sigma; reads staged q/k (g_sq/g_sk raw), writes splits ----------------
__global__ __launch_bounds__(256) void rope_kernel(const int* __restrict__ pos)
{
    int t = threadIdx.x;
    long rid = (long)blockIdx.x*2 + (t>>7);
    int d = t & 127;
    int s  = (int)(rid & (SS-1));
    int bh = (int)(rid >> 11);
    int b  = bh >> 4;
    size_t base = (size_t)rid * DD;
    float qv = g_sq[base+d], kv = g_sk[base+d];
    float qo = (d<64)? -g_sq[base+d+64] : g_sq[base+d-64];
    float ko = (d<64)? -g_sk[base+d+64] : g_sk[base+d-64];
    int p = pos[(size_t)b*SS + s];
    float inv = expf(-0.14391156831212787f * (float)(d & 63));
    float ang = (float)p * inv;
    float sn, cs;
    sincosf(ang, &sn, &cs);
    float qn = qv*cs + qo*sn;
    float kn = kv*cs + ko*sn;
    float sq = (qn>0.f) ? qn+1.f : expf(qn);
    float sk = (kn>0.f) ? kn+1.f : expf(kn);
    __syncthreads();   // all reads of this row done before overwrite
    g_sq[base+d] = sq;
    g_sk[base+d] = sk;
    __nv_bfloat16 h,l;
    bf16split(qn,h,l); g_qH[base+d]=h;  g_qL[base+d]=l;
    bf16split(kn,h,l); g_kH[base+d]=h;  g_kL[base+d]=l;
    bf16split(sq,h,l); g_sqH[base+d]=h; g_sqL[base+d]=l;
}

// ---------------- den[row] = dot(sig_q[row], z[h]) ----------------
__global__ __launch_bounds__(256) void den_kernel(const float* __restrict__ z)
{
    int wid = threadIdx.x>>5, lane = threadIdx.x&31;
    int row = blockIdx.x*8 + wid;
    int h = (row>>11)&15;
    const float4* sq = (const float4*)(g_sq + (size_t)row*DD);
    const float4* zz = (const float4*)(z + h*DD);
    float4 a = sq[lane], b = zz[lane];
    float dot = a.x*b.x + a.y*b.y + a.z*b.z + a.w*b.w;
    #pragma unroll
    for (int o=16;o>0;o>>=1) dot += __shfl_down_sync(0xffffffffu, dot, o);
    if (lane==0) g_den[row] = dot;
}

// ---------------- memory retrieval via HMMA: (sig_q @ M[h]) / den ----------------
#define MR_TILE (128*136*2)   // bytes per bf16 tile
__global__ __launch_bounds__(256) void memret_mma_kernel()
{
    extern __shared__ char sm[];
    uint32_t sb = smem_u32(sm);
    float* denS = (float*)(sm + 4*MR_TILE);
    int s0 = blockIdx.x * 128;
    int bh = blockIdx.y;
    int h  = bh & 15;
    int t = threadIdx.x, wid=t>>5, lane=t&31;
    int wm = wid>>2, wn = wid&3;
    size_t rowbase = (size_t)bh*SS + s0;

    // FIX (round-7/9 bug): one head of Mt = 128*128 bf16 = 2048 uint4 (was h*1024)
    const uint4* srcs[4] = {
        (const uint4*)g_sqH + rowbase*16, (const uint4*)g_sqL + rowbase*16,
        (const uint4*)g_MtH + (size_t)h*2048, (const uint4*)g_MtL + (size_t)h*2048 };
    uint4* s4 = (uint4*)sm;
    #pragma unroll
    for (int i=0;i<32;i++){
        int slot = t + i*256;           // 8192
        int sp = slot>>11, r = (slot>>4)&127, c16 = slot&15;
        s4[sp*(MR_TILE/16) + r*17 + c16] = srcs[sp][(size_t)r*16 + c16];
    }
    if (t < 128) denS[t] = g_den[rowbase + t];
    __syncthreads();

    float acc[4][4][4];
    #pragma unroll
    for (int mt=0;mt<4;mt++)
        #pragma unroll
        for (int nt=0;nt<4;nt++)
            #pragma unroll
            for (int e=0;e<4;e++) acc[mt][nt][e]=0.f;

    uint32_t aRow = (uint32_t)(wm*64 + (lane&15));
    uint32_t aChk = (uint32_t)(lane>>4);
    uint32_t bRow = (uint32_t)(wn*32 + (lane&7));
    uint32_t bChk = (uint32_t)((lane>>3)&1);

    #pragma unroll
    for (int kf=0; kf<8; kf++){
        uint32_t aH[4][4], aL[4][4], bH[4][2], bL[4][2];
        #pragma unroll
        for (int mt=0;mt<4;mt++){
            uint32_t off = (aRow + mt*16)*272u + (kf*2 + aChk)*16u;
            ldsm_x4(aH[mt][0],aH[mt][1],aH[mt][2],aH[mt][3], sb + 0*MR_TILE + off);
            ldsm_x4(aL[mt][0],aL[mt][1],aL[mt][2],aL[mt][3], sb + 1*MR_TILE + off);
        }
        #pragma unroll
        for (int nt=0;nt<4;nt++){
            uint32_t off = (bRow + nt*8)*272u + (kf*2 + bChk)*16u;
            ldsm_x2(bH[nt][0],bH[nt][1], sb + 2*MR_TILE + off);
            ldsm_x2(bL[nt][0],bL[nt][1], sb + 3*MR_TILE + off);
        }
        #pragma unroll
        for (int mt=0;mt<4;mt++)
            #pragma unroll
            for (int nt=0;nt<4;nt++){
                mma_bf16(acc[mt][nt], aH[mt], bH[nt]);
                mma_bf16(acc[mt][nt], aH[mt], bL[nt]);
                mma_bf16(acc[mt][nt], aL[mt], bH[nt]);
            }
    }

    int rB = wm*64 + (lane>>2);
    int cB = wn*32 + (lane&3)*2;
    size_t obase = ((size_t)bh*SS + s0)*DD;
    #pragma unroll
    for (int mt=0;mt<4;mt++)
        #pragma unroll
        for (int nt=0;nt<4;nt++)
            #pragma unroll
            for (int half=0; half<2; half++){
                int row = rB + mt*16 + half*8;
                int col = cB + nt*8;
                float dinv = 1.f/denS[row];
                g_mem[obase + (size_t)row*DD + col]   = acc[mt][nt][half*2+0]*dinv;
                g_mem[obase + (size_t)row*DD + col+1] = acc[mt][nt][half*2+1]*dinv;
            }
}

// ---------------- flash attention via HMMA, split precision ----------------
#define FQ_H 0
#define FQ_L 34816
#define FK_H 69632
#define FK_L 87040
#define FVT_H 104448
#define FVT_L 122880
#define FPS 141312
#define FP_H 174592
#define FP_L 193024
#define FMR 211456
#define FTOT 212992

__global__ __launch_bounds__(256,1) void attn_mma_kernel()
{
    extern __shared__ char sm[];
    uint32_t sb = smem_u32(sm);
    float* PS   = (float*)(sm + FPS);
    __nv_bfloat16* VTH = (__nv_bfloat16*)(sm + FVT_H);
    __nv_bfloat16* VTL = (__nv_bfloat16*)(sm + FVT_L);
    __nv_bfloat16* PH  = (__nv_bfloat16*)(sm + FP_H);
    __nv_bfloat16* PL  = (__nv_bfloat16*)(sm + FP_L);
    float* mrow = (float*)(sm + FMR);
    float* lrow = mrow + 128;
    float* rs   = lrow + 128;

    int qb = blockIdx.x, bh = blockIdx.y;
    int t = threadIdx.x, wid=t>>5, lane=t&31;
    int wm = wid>>2, wn = wid&3;
    size_t rowbase = (size_t)bh*SS;
    size_t base = rowbase*DD;

    // Q splits: 4096 uint4
    {
        uint4* s4 = (uint4*)sm;
        const uint4* q4[2] = { (const uint4*)g_qH + (rowbase + qb*128)*16,
                               (const uint4*)g_qL + (rowbase + qb*128)*16 };
        #pragma unroll
        for (int i=0;i<16;i++){
            int slot = t + i*256;
            int sp = slot>>11, r = (slot>>4)&127, c16 = slot&15;
            s4[(sp*34816)/16 + r*17 + c16] = q4[sp][(size_t)r*16 + c16];
        }
    }
    if (t < 128){ mrow[t] = -INFINITY; lrow[t] = 0.f; }

    float oacc[4][4][4];
    #pragma unroll
    for (int mt=0;mt<4;mt++)
        #pragma unroll
        for (int nt=0;nt<4;nt++)
            #pragma unroll
            for (int e=0;e<4;e++) oacc[mt][nt][e]=0.f;
    __syncthreads();

    const float sscale = 0.08838834764831845f;
    uint32_t aRow = (uint32_t)(wm*64 + (lane&15));
    uint32_t aChk = (uint32_t)(lane>>4);
    uint32_t bRowS = (uint32_t)(wn*16 + (lane&7));   // S phase: n-tile 16
    uint32_t bRowV = (uint32_t)(wn*32 + (lane&7));   // PV phase: n-tile 32
    uint32_t bChk = (uint32_t)((lane>>3)&1);
    int rB = wm*64 + (lane>>2);

    int jbmax = 2*qb + 1;
    for (int jb=0; jb<=jbmax; jb++){
        // K tiles: 2048 uint4
        {
            uint4* s4 = (uint4*)(sm + FK_H);
            const uint4* k4[2] = { (const uint4*)g_kH + (rowbase + jb*64)*16,
                                   (const uint4*)g_kL + (rowbase + jb*64)*16 };
            #pragma unroll
            for (int i=0;i<8;i++){
                int slot = t + i*256;
                int sp = slot>>10, r = (slot>>4)&63, c16 = slot&15;
                s4[(sp*17408)/16 + r*17 + c16] = k4[sp][(size_t)r*16 + c16];
            }
        }
        // V transpose+split: [64 s][128 d] -> VT [d][s] stride 72
        #pragma unroll
        for (int i=0;i<32;i++){
            int e = i*256 + t;
            int s = e>>7, d = e&127;
            float v = g_v[base + (size_t)(jb*64+s)*DD + d];
            __nv_bfloat16 h,l; bf16split(v,h,l);
            VTH[d*72 + s] = h; VTL[d*72 + s] = l;
        }
        __syncthreads();

        // S = Q K^T (3-pass)
        float sacc[4][2][4];
        #pragma unroll
        for (int mt=0;mt<4;mt++)
            #pragma unroll
            for (int nt=0;nt<2;nt++)
                #pragma unroll
                for (int e=0;e<4;e++) sacc[mt][nt][e]=0.f;
        #pragma unroll
        for (int kf=0; kf<8; kf++){
            uint32_t aH[4][4], aL[4][4], bH[2][2], bL[2][2];
            #pragma unroll
            for (int mt=0;mt<4;mt++){
                uint32_t off = (aRow + mt*16)*272u + (kf*2 + aChk)*16u;
                ldsm_x4(aH[mt][0],aH[mt][1],aH[mt][2],aH[mt][3], sb + FQ_H + off);
                ldsm_x4(aL[mt][0],aL[mt][1],aL[mt][2],aL[mt][3], sb + FQ_L + off);
            }
            #pragma unroll
            for (int nt=0;nt<2;nt++){
                uint32_t off = (bRowS + nt*8)*272u + (kf*2 + bChk)*16u;
                ldsm_x2(bH[nt][0],bH[nt][1], sb + FK_H + off);
                ldsm_x2(bL[nt][0],bL[nt][1], sb + FK_L + off);
            }
            #pragma unroll
            for (int mt=0;mt<4;mt++)
                #pragma unroll
                for (int nt=0;nt<2;nt++){
                    mma_bf16(sacc[mt][nt], aH[mt], bH[nt]);
                    mma_bf16(sacc[mt][nt], aH[mt], bL[nt]);
                    mma_bf16(sacc[mt][nt], aL[mt], bH[nt]);
                }
        }
        // store S -> PS with mask & scale
        {
            int cBs = wn*16 + (lane&3)*2;
            #pragma unroll
            for (int mt=0;mt<4;mt++)
                #pragma unroll
                for (int nt=0;nt<2;nt++)
                    #pragma unroll
                    for (int half=0; half<2; half++){
                        int row = rB + mt*16 + half*8;
                        int col = cBs + nt*8;
                        int qrow = qb*128 + row, kcol = jb*64 + col;
                        PS[row*65+col]   = (kcol   <= qrow) ? sacc[mt][nt][half*2+0]*sscale : -INFINITY;
                        PS[row*65+col+1] = (kcol+1 <= qrow) ? sacc[mt][nt][half*2+1]*sscale : -INFINITY;
                    }
        }
        __syncthreads();

        // online softmax (row-serial, fp32)
        if (t < 128){
            float m_old = mrow[t], l_old = lrow[t];
            float tmax = -INFINITY;
            #pragma unroll 8
            for (int j=0;j<64;j++) tmax = fmaxf(tmax, PS[t*65+j]);
            float m_new = fmaxf(m_old, tmax);
            float sc = __expf(m_old - m_new);
            float sum = 0.f;
            #pragma unroll 8
            for (int j=0;j<64;j++){
                float p = __expf(PS[t*65+j] - m_new);
                PS[t*65+j] = p;
                sum += p;
            }
            mrow[t] = m_new;
            lrow[t] = sc*l_old + sum;
            rs[t]   = sc;
        }
        __syncthreads();

        // split P -> bf16 (stride 72)
        #pragma unroll
        for (int i=0;i<32;i++){
            int e = i*256 + t;
            int row = e>>6, col = e&63;
            __nv_bfloat16 h,l; bf16split(PS[row*65+col], h, l);
            PH[row*72+col] = h; PL[row*72+col] = l;
        }
        __syncthreads();

        // rescale O, then O += P V (3-pass)
        #pragma unroll
        for (int mt=0;mt<4;mt++){
            float s0 = rs[rB + mt*16], s1 = rs[rB + mt*16 + 8];
            #pragma unroll
            for (int nt=0;nt<4;nt++){
                oacc[mt][nt][0] *= s0; oacc[mt][nt][1] *= s0;
                oacc[mt][nt][2] *= s1; oacc[mt][nt][3] *= s1;
            }
        }
        #pragma unroll
        for (int kf=0; kf<4; kf++){
            uint32_t aH[4][4], aL[4][4], bH[4][2], bL[4][2];
            #pragma unroll
            for (int mt=0;mt<4;mt++){
                uint32_t off = (aRow + mt*16)*144u + (kf*2 + aChk)*16u;
                ldsm_x4(aH[mt][0],aH[mt][1],aH[mt][2],aH[mt][3], sb + FP_H + off);
                ldsm_x4(aL[mt][0],aL[mt][1],aL[mt][2],aL[mt][3], sb + FP_L + off);
            }
            #pragma unroll
            for (int nt=0;nt<4;nt++){
                uint32_t off = (bRowV + nt*8)*144u + (kf*2 + bChk)*16u;
                ldsm_x2(bH[nt][0],bH[nt][1], sb + FVT_H + off);
                ldsm_x2(bL[nt][0],bL[nt][1], sb + FVT_L + off);
            }
            #pragma unroll
            for (int mt=0;mt<4;mt++)
                #pragma unroll
                for (int nt=0;nt<4;nt++){
                    mma_bf16(oacc[mt][nt], aH[mt], bH[nt]);
                    mma_bf16(oacc[mt][nt], aH[mt], bL[nt]);
                    mma_bf16(oacc[mt][nt], aL[mt], bH[nt]);
                }
        }
        __syncthreads();
    }

    // final normalize + store
    int cB = wn*32 + (lane&3)*2;
    #pragma unroll
    for (int mt=0;mt<4;mt++)
        #pragma unroll
        for (int half=0; half<2; half++){
            int row = rB + mt*16 + half*8;
            float linv = 1.f/lrow[row];
            #pragma unroll
            for (int nt=0;nt<4;nt++){
                int col = cB + nt*8;
                size_t o = base + (size_t)(qb*128+row)*DD + col;
                g_att[o]   = oacc[mt][nt][half*2+0]*linv;
                g_att[o+1] = oacc[mt][nt][half*2+1]*linv;
            }
        }
}

// ---------------- M update via HMMA: partials per (h, 256-row chunk) ----------------
__global__ __launch_bounds__(256) void m_update_mma_kernel()
{
    __shared__ __nv_bfloat16 skTH[128*40], skTL[128*40], vTH[128*40], vTL[128*40];
    __shared__ float zred[256];
    uint32_t sA_H = smem_u32(skTH), sA_L = smem_u32(skTL);
    uint32_t sB_H = smem_u32(vTH),  sB_L = smem_u32(vTL);

    int h = blockIdx.x, c = blockIdx.y;
    int b = c>>3, s0 = (c&7)*256;
    size_t base = (((size_t)(b*HH + h))*SS + s0)*DD;
    int t = threadIdx.x, wid=t>>5, lane=t&31;
    int wm = wid>>2, wn = wid&3;

    float acc[4][4][4];
    #pragma unroll
    for (int mt=0;mt<4;mt++)
        #pragma unroll
        for (int nt=0;nt<4;nt++)
            #pragma unroll
            for (int e=0;e<4;e++) acc[mt][nt][e]=0.f;
    float zacc = 0.f;

    uint32_t aRow = (uint32_t)(wm*64 + (lane&15));
    uint32_t aChk = (uint32_t)(lane>>4);
    uint32_t bRow = (uint32_t)(wn*32 + (lane&7));
    uint32_t bChk = (uint32_t)((lane>>3)&1);

    for (int kc=0; kc<8; kc++){
        // transpose+split 32x128 chunks of sk and v
        #pragma unroll
        for (int i=0;i<16;i++){
            int e = i*256 + t;
            int s = e>>7, d = e&127;
            size_t g = base + (size_t)(kc*32+s)*DD + d;
            float sv = g_sk[g], vv = g_v[g];
            __nv_bfloat16 hh,ll;
            bf16split(sv,hh,ll); skTH[d*40+s]=hh; skTL[d*40+s]=ll;
            bf16split(vv,hh,ll); vTH[d*40+s]=hh;  vTL[d*40+s]=ll;
            zacc += sv;   // d = t&127, invariant per thread
        }
        __syncthreads();

        #pragma unroll
        for (int kf=0; kf<2; kf++){
            uint32_t aH[4][4], aL[4][4], bH[4][2], bL[4][2];
            #pragma unroll
            for (int mt=0;mt<4;mt++){
                uint32_t off = (aRow + mt*16)*80u + (kf*2 + aChk)*16u;
                ldsm_x4(aH[mt][0],aH[mt][1],aH[mt][2],aH[mt][3], sA_H + off);
                ldsm_x4(aL[mt][0],aL[mt][1],aL[mt][2],aL[mt][3], sA_L + off);
            }
            #pragma unroll
            for (int nt=0;nt<4;nt++){
                uint32_t off = (bRow + nt*8)*80u + (kf*2 + bChk)*16u;
                ldsm_x2(bH[nt][0],bH[nt][1], sB_H + off);
                ldsm_x2(bL[nt][0],bL[nt][1], sB_L + off);
            }
            #pragma unroll
            for (int mt=0;mt<4;mt++)
                #pragma unroll
                for (int nt=0;nt<4;nt++){
                    mma_bf16(acc[mt][nt], aH[mt], bH[nt]);
                    mma_bf16(acc[mt][nt], aH[mt], bL[nt]);
                    mma_bf16(acc[mt][nt], aL[mt], bH[nt]);
                }
        }
        __syncthreads();
    }

    zred[t] = zacc;
    __syncthreads();
    if (t < 128) g_zpart[(h*16 + c)*DD + t] = zred[t] + zred[t+128];

    size_t pbase = ((size_t)(h*16 + c)) << 14;
    int rB = wm*64 + (lane>>2);
    int cB = wn*32 + (lane&3)*2;
    #pragma unroll
    for (int mt=0;mt<4;mt++)
        #pragma unroll
        for (int nt=0;nt<4;nt++)
            #pragma unroll
            for (int half=0; half<2; half++){
                int row = rB + mt*16 + half*8;   // d
                int col = cB + nt*8;              // e
                g_mpart[pbase + (size_t)row*DD + col]   = acc[mt][nt][half*2+0];
                g_mpart[pbase + (size_t)row*DD + col+1] = acc[mt][nt][half*2+1];
            }
}

__global__ void reduce_m_kernel(const float* __restrict__ M, float* __restrict__ out)
{
    int idx = blockIdx.x*256 + threadIdx.x;
    int h = idx >> 14;
    int de = idx & 16383;
    float s = M[idx];
    #pragma unroll
    for (int c=0;c<16;c++) s += g_mpart[(((size_t)(h*16+c))<<14) + de];
    out[idx] = s;
}

__global__ void reduce_z_kernel(const float* __restrict__ z, float* __restrict__ out)
{
    int idx = blockIdx.x*256 + threadIdx.x;
    float s = z[idx];
    int h = idx >> 7, d = idx & 127;
    #pragma unroll
    for (int c=0;c<16;c++) s += g_zpart[(h*16+c)*DD + d];
    out[idx] = s;
}

// ---------------- launch ----------------
extern "C" void kernel_launch(void* const* d_in, const int* in_sizes, int n_in,
                              void* d_out, int out_size)
{
    (void)in_sizes; (void)n_in; (void)out_size;
    const float* hs   = (const float*)d_in[0];
    const float* Wq   = (const float*)d_in[1];
    const float* bq   = (const float*)d_in[2];
    const float* Wk   = (const float*)d_in[3];
    const float* bk   = (const float*)d_in[4];
    const float* Wv   = (const float*)d_in[5];
    const float* bv   = (const float*)d_in[6];
    const float* Wo   = (const float*)d_in[7];
    const float* beta = (const float*)d_in[8];
    const float* Mm   = (const float*)d_in[9];
    const float* zz   = (const float*)d_in[10];
    const int* pos    = (const int*)d_in[12];
    float* out = (float*)d_out;

    cudaFuncSetAttribute(attn_mma_kernel, cudaFuncAttributeMaxDynamicSharedMemorySize, FTOT);
    cudaFuncSetAttribute(memret_mma_kernel, cudaFuncAttributeMaxDynamicSharedMemorySize, 4*MR_TILE + 512);

    // splits + transposes of inputs
    split_a_kernel<<<MTOT*HIDN/256, 256>>>(hs);
    wsplit_kernel<<<dim3(64,64,4), 256>>>(Wq, Wk, Wv, Wo);
    msplit_kernel<<<1024, 256>>>(Mm);

    // QKV (q->g_sq staging, k->g_sk staging, v->g_v)
    gemm_mma_kernel<<<dim3(16,32,3), 256>>>(bq, bk, bv, nullptr, 0);

    // rope: consumes staged q/k, emits bf16 splits + sigma
    rope_kernel<<<BHS/2, 256>>>(pos);

    den_kernel<<<BHS/8, 256>>>(zz);
    memret_mma_kernel<<<dim3(16,32), 256, 4*MR_TILE + 512>>>();

    attn_mma_kernel<<<dim3(16,32), 256, FTOT>>>();

    m_update_mma_kernel<<<dim3(16,16), 256>>>();
    reduce_m_kernel<<<1024, 256>>>(Mm, out + 8388608);
    reduce_z_kernel<<<8, 256>>>(zz, out + 8388608 + 262144);

    combine_split_kernel<<<MTOT*HIDN/256, 256>>>(beta);
    gemm_mma_kernel<<<dim3(16,32,1), 256>>>(bq, bk, bv, out, 1);
}

// round 12
// speedup vs baseline: 2.6340x; 1.0347x over previous
#include <cuda_runtime.h>
#include <cuda_bf16.h>
#include <math.h>
#include <stdint.h>

#define BB 2
#define SS 2048
#define HH 16
#define DD 128
#define HIDN 2048
#define BHS (BB*HH*SS)          // 65536 rows of length D
#define MTOT 4096               // B*S rows

// ---------------- scratch (static device globals; no allocation) ----------------
__device__ float g_v  [BB*HH*SS*DD];
__device__ float g_sq [BB*HH*SS*DD];
__device__ float g_sk [BB*HH*SS*DD];
__device__ float g_mem[BB*HH*SS*DD];
__device__ float g_att[BB*HH*SS*DD];
__device__ float g_den[BHS];
__device__ float g_mpart[HH*16*DD*DD];
__device__ float g_zpart[HH*16*DD];

// bf16 split-precision operands
__device__ __nv_bfloat16 g_AH[MTOT*HIDN];
__device__ __nv_bfloat16 g_AL[MTOT*HIDN];
__device__ __nv_bfloat16 g_WtH[4u*HIDN*HIDN];   // [which][n][k] transposed
__device__ __nv_bfloat16 g_WtL[4u*HIDN*HIDN];
__device__ __nv_bfloat16 g_CH[MTOT*HIDN];       // gated combine, split
__device__ __nv_bfloat16 g_CL[MTOT*HIDN];
__device__ __nv_bfloat16 g_qH[BB*HH*SS*DD];     // post-rope q/k splits
__device__ __nv_bfloat16 g_qL[BB*HH*SS*DD];
__device__ __nv_bfloat16 g_kH[BB*HH*SS*DD];
__device__ __nv_bfloat16 g_kL[BB*HH*SS*DD];
__device__ __nv_bfloat16 g_sqH[BB*HH*SS*DD];    // sigma(q) splits
__device__ __nv_bfloat16 g_sqL[BB*HH*SS*DD];
__device__ __nv_bfloat16 g_MtH[HH*DD*DD];       // M transposed [h][e][d] splits
__device__ __nv_bfloat16 g_MtL[HH*DD*DD];
__device__ __nv_bfloat16 g_vTH[BB*HH*SS*DD];    // V transposed [bh][d][s] splits
__device__ __nv_bfloat16 g_vTL[BB*HH*SS*DD];

// ================= mma.sync helpers (validated round 6) =================
__device__ __forceinline__ uint32_t smem_u32(const void* p){
    return (uint32_t)__cvta_generic_to_shared(p);
}
__device__ __forceinline__ void ldsm_x4(uint32_t& r0, uint32_t& r1, uint32_t& r2, uint32_t& r3, uint32_t addr){
    asm volatile("ldmatrix.sync.aligned.m8n8.x4.shared.b16 {%0,%1,%2,%3}, [%4];"
        : "=r"(r0), "=r"(r1), "=r"(r2), "=r"(r3) : "r"(addr));
}
__device__ __forceinline__ void ldsm_x2(uint32_t& r0, uint32_t& r1, uint32_t addr){
    asm volatile("ldmatrix.sync.aligned.m8n8.x2.shared.b16 {%0,%1}, [%2];"
        : "=r"(r0), "=r"(r1) : "r"(addr));
}
__device__ __forceinline__ void mma_bf16(float* d, const uint32_t* a, const uint32_t* b){
    asm volatile("mma.sync.aligned.m16n8k16.row.col.f32.bf16.bf16.f32 "
        "{%0,%1,%2,%3}, {%4,%5,%6,%7}, {%8,%9}, {%0,%1,%2,%3};"
        : "+f"(d[0]), "+f"(d[1]), "+f"(d[2]), "+f"(d[3])
        : "r"(a[0]), "r"(a[1]), "r"(a[2]), "r"(a[3]), "r"(b[0]), "r"(b[1]));
}
__device__ __forceinline__ void bf16split(float v, __nv_bfloat16& h, __nv_bfloat16& l){
    h = __float2bfloat16_rn(v);
    l = __float2bfloat16_rn(v - __bfloat162float(h));
}

// ================= pre-pass kernels =================
__global__ __launch_bounds__(256) void split_a_kernel(const float* __restrict__ A)
{
    int idx = blockIdx.x*256 + threadIdx.x;
    __nv_bfloat16 h,l; bf16split(A[idx], h, l);
    g_AH[idx] = h; g_AL[idx] = l;
}

__global__ __launch_bounds__(256) void wsplit_kernel(
    const float* __restrict__ Wq, const float* __restrict__ Wk,
    const float* __restrict__ Wv, const float* __restrict__ Wo)
{
    __shared__ float tile[32][33];
    int z = blockIdx.z;
    const float* W = (z==0)?Wq:((z==1)?Wk:((z==2)?Wv:Wo));
    __nv_bfloat16* H = g_WtH + (size_t)z*HIDN*HIDN;
    __nv_bfloat16* L = g_WtL + (size_t)z*HIDN*HIDN;
    int n0 = blockIdx.x*32, k0 = blockIdx.y*32;
    int tx = threadIdx.x & 31, ty = threadIdx.x >> 5;
    #pragma unroll
    for (int i=0;i<4;i++)
        tile[ty+8*i][tx] = W[(size_t)(k0+ty+8*i)*HIDN + n0+tx];
    __syncthreads();
    #pragma unroll
    for (int i=0;i<4;i++){
        __nv_bfloat16 h,l; bf16split(tile[tx][ty+8*i], h, l);
        size_t o = (size_t)(n0+ty+8*i)*HIDN + k0+tx;
        H[o] = h; L[o] = l;
    }
}

// transpose+split M: src [h][d][e] -> dst [h][e][d]
__global__ __launch_bounds__(256) void msplit_kernel(const float* __restrict__ M)
{
    int idx = blockIdx.x*256 + threadIdx.x;   // 262144
    int h = idx >> 14, d = (idx>>7)&127, e = idx&127;
    __nv_bfloat16 hh,ll; bf16split(M[idx], hh, ll);
    size_t o = (size_t)h*16384 + e*128 + d;
    g_MtH[o] = hh; g_MtL[o] = ll;
}

__global__ __launch_bounds__(256) void combine_split_kernel(const float* __restrict__ beta)
{
    int idx = blockIdx.x*256 + threadIdx.x;
    float g = 1.f/(1.f + expf(-beta[0]));
    int m = idx >> 11, kcol = idx & 2047;
    int b = m>>11, s = m&2047, h = kcol>>7, d = kcol&127;
    size_t a = (((size_t)(b*HH+h))*SS + s)*DD + d;
    float v = g*g_mem[a] + (1.f-g)*g_att[a];
    __nv_bfloat16 hh,ll; bf16split(v, hh, ll);
    g_CH[idx] = hh; g_CL[idx] = ll;
}

// transpose+split V: [bh][s][d] fp32 -> [bh][d][s] bf16 H/L.
// Pair-packing: two adjacent s into one uint32 -> conflict-free stride-66 smem.
#define VT_SMEM (2*128*66*4)
__global__ __launch_bounds__(256) void vsplitT_kernel()
{
    extern __shared__ char sm[];
    uint32_t* sH = (uint32_t*)sm;            // [128 d][66]
    uint32_t* sL = sH + 128*66;
    int bh = blockIdx.x, sc0 = blockIdx.y*128;
    int t = threadIdx.x;
    size_t base = ((size_t)bh*SS + sc0)*DD;
    #pragma unroll
    for (int i=0;i<32;i++){
        int pidx = i*256 + t;      // 8192 pairs
        int d = pidx & 127, sp = pidx >> 7;   // sp 0..63
        float v0 = g_v[base + (size_t)(2*sp)*DD + d];
        float v1 = g_v[base + (size_t)(2*sp+1)*DD + d];
        __nv_bfloat16 h0,l0,h1,l1;
        bf16split(v0,h0,l0); bf16split(v1,h1,l1);
        uint32_t ph = ((uint32_t)__bfloat16_as_ushort(h1)<<16) | (uint32_t)__bfloat16_as_ushort(h0);
        uint32_t pl = ((uint32_t)__bfloat16_as_ushort(l1)<<16) | (uint32_t)__bfloat16_as_ushort(l0);
        sH[d*66 + sp] = ph;
        sL[d*66 + sp] = pl;
    }
    __syncthreads();
    #pragma unroll
    for (int i=0;i<16;i++){
        int flat = i*256 + t;      // 4096 = 128 d x 32 c2
        int d = flat>>5, c2 = flat&31;
        uint2 vh = *(uint2*)&sH[d*66 + c2*2];
        uint2 vl = *(uint2*)&sL[d*66 + c2*2];
        size_t o32 = ((size_t)(bh*128+d)*2048 + sc0)/2 + c2*2;
        *(uint2*)((uint32_t*)g_vTH + o32) = vh;
        *(uint2*)((uint32_t*)g_vTL + o32) = vl;
    }
}

// ================= HMMA GEMM (round 6) + double-buffered smem =================
#define TSTRIDE 40
#define TILE_BF16 (128*TSTRIDE)
#define TILE_U4   (TILE_BF16/8)
#define GEMM_SMEM (2*4*TILE_BF16*2)   // 81920 B

__global__ __launch_bounds__(256) void gemm_mma_kernel(
    const float* __restrict__ bq, const float* __restrict__ bk, const float* __restrict__ bv,
    float* __restrict__ outp, int asel)
{
    extern __shared__ char sm[];
    uint32_t sbase = smem_u32(sm);
    uint4* s4 = (uint4*)sm;

    int t = threadIdx.x;
    int wid = t>>5, lane = t&31;
    int wm = wid>>2, wn = wid&3;
    int n0 = blockIdx.x*128;
    int m0 = blockIdx.y*128;
    int which = (asel==0) ? blockIdx.z : 3;
    const __nv_bfloat16* Ah = (asel==0) ? g_AH : g_CH;
    const __nv_bfloat16* Al = (asel==0) ? g_AL : g_CL;
    const __nv_bfloat16* Bh = g_WtH + (size_t)which*HIDN*HIDN;
    const __nv_bfloat16* Bl = g_WtL + (size_t)which*HIDN*HIDN;

    const __nv_bfloat16* gsrc[4] = {
        Ah + (size_t)m0*HIDN, Al + (size_t)m0*HIDN,
        Bh + (size_t)n0*HIDN, Bl + (size_t)n0*HIDN };

    int tt[8], rr[8], cc[8];
    #pragma unroll
    for (int i=0;i<8;i++){
        int slot = t + i*256;
        tt[i] = slot>>9;
        int w = slot&511;
        rr[i] = w>>2;
        cc[i] = w&3;
    }

    float acc[4][4][4];
    #pragma unroll
    for (int mt=0;mt<4;mt++)
        #pragma unroll
        for (int nt=0;nt<4;nt++)
            #pragma unroll
            for (int e=0;e<4;e++) acc[mt][nt][e] = 0.f;

    uint32_t aRow = (uint32_t)(wm*64 + (lane&15));
    uint32_t aChk = (uint32_t)(lane>>4);
    uint32_t bRow = (uint32_t)(wn*32 + (lane&7));
    uint32_t bChk = (uint32_t)((lane>>3)&1);

    uint4 buf[8];
    // preload chunk 0 -> buffer 0
    #pragma unroll
    for (int i=0;i<8;i++)
        buf[i] = *(const uint4*)(gsrc[tt[i]] + (size_t)rr[i]*HIDN + cc[i]*8);
    #pragma unroll
    for (int i=0;i<8;i++)
        s4[tt[i]*TILE_U4 + rr[i]*5 + cc[i]] = buf[i];
    __syncthreads();

    for (int kt=0; kt<64; kt++){
        int cur = kt & 1;
        // prefetch next chunk (LDGs in flight during MMAs)
        if (kt < 63){
            int k0 = (kt+1)*32;
            #pragma unroll
            for (int i=0;i<8;i++)
                buf[i] = *(const uint4*)(gsrc[tt[i]] + (size_t)rr[i]*HIDN + k0 + cc[i]*8);
        }

        uint32_t bufb = sbase + (uint32_t)cur*(4*TILE_BF16*2);
        #pragma unroll
        for (int k16=0;k16<2;k16++){
            uint32_t aH[4][4], aL[4][4], bH[4][2], bL[4][2];
            #pragma unroll
            for (int mt=0;mt<4;mt++){
                uint32_t off = (aRow + mt*16)*80u + (k16*2 + aChk)*16u;
                ldsm_x4(aH[mt][0],aH[mt][1],aH[mt][2],aH[mt][3], bufb + 0*TILE_BF16*2 + off);
                ldsm_x4(aL[mt][0],aL[mt][1],aL[mt][2],aL[mt][3], bufb + 1*TILE_BF16*2 + off);
            }
            #pragma unroll
            for (int nt=0;nt<4;nt++){
                uint32_t off = (bRow + nt*8)*80u + (k16*2 + bChk)*16u;
                ldsm_x2(bH[nt][0],bH[nt][1], bufb + 2*TILE_BF16*2 + off);
                ldsm_x2(bL[nt][0],bL[nt][1], bufb + 3*TILE_BF16*2 + off);
            }
            #pragma unroll
            for (int mt=0;mt<4;mt++)
                #pragma unroll
                for (int nt=0;nt<4;nt++){
                    mma_bf16(acc[mt][nt], aH[mt], bH[nt]);
                    mma_bf16(acc[mt][nt], aH[mt], bL[nt]);
                    mma_bf16(acc[mt][nt], aL[mt], bH[nt]);
                }
        }
        // store prefetched chunk into the other buffer
        if (kt < 63){
            int nb = (cur^1)*4*TILE_U4;
            #pragma unroll
            for (int i=0;i<8;i++)
                s4[nb + tt[i]*TILE_U4 + rr[i]*5 + cc[i]] = buf[i];
        }
        __syncthreads();
    }

    int rB = wm*64 + (lane>>2);
    int cB = wn*32 + (lane&3)*2;
    if (asel == 0){
        const float* bias = (which==0)?bq:((which==1)?bk:bv);
        int h = n0>>7;
        #pragma unroll
        for (int mt=0;mt<4;mt++){
            #pragma unroll
            for (int nt=0;nt<4;nt++){
                int row = rB + mt*16;
                int col = cB + nt*8;
                int n = n0 + col;
                #pragma unroll
                for (int half=0; half<2; half++){
                    int m = m0 + row + half*8;
                    int b = m>>11, s = m&2047;
                    size_t o = (((size_t)(b*HH+h))*SS + s)*DD + col;
                    float v0 = acc[mt][nt][half*2+0] + bias[n];
                    float v1 = acc[mt][nt][half*2+1] + bias[n+1];
                    if (which == 2){            // V: fp32
                        g_v[o] = v0; g_v[o+1] = v1;
                    } else {                     // Q/K staging pre-rope
                        float* O = (which==0)?g_sq:g_sk;
                        O[o] = v0; O[o+1] = v1;
                    }
                }
            }
        }
    } else {
        #pragma unroll
        for (int mt=0;mt<4;mt++){
            #pragma unroll
            for (int nt=0;nt<4;nt++){
                int row = rB + mt*16;
                int col = cB + nt*8;
                #pragma unroll
                for (int half=0; half<2; half++){
                    size_t o = (size_t)(m0 + row + half*8)*HIDN + n0 + col;
                    outp[o]   = acc[mt][nt][half*2+0];
                    outp[o+1] = acc[mt][nt][half*2+1];
                }
            }
        }
    }
}

// ---------------- RoPE + sigma; reads staged q/k (g_sq/g_sk raw), writes splits ----------------
__global__ __launch_bounds__(256) void rope_kernel(const int* __restrict__ pos)
{
    int t = threadIdx.x;
    long rid = (long)blockIdx.x*2 + (t>>7);
    int d = t & 127;
    int s  = (int)(rid & (SS-1));
    int bh = (int)(rid >> 11);
    int b  = bh >> 4;
    size_t base = (size_t)rid * DD;
    float qv = g_sq[base+d], kv = g_sk[base+d];
    float qo = (d<64)? -g_sq[base+d+64] : g_sq[base+d-64];
    float ko = (d<64)? -g_sk[base+d+64] : g_sk[base+d-64];
    int p = pos[(size_t)b*SS + s];
    float inv = expf(-0.14391156831212787f * (float)(d & 63));
    float ang = (float)p * inv;
    float sn, cs;
    sincosf(ang, &sn, &cs);
    float qn = qv*cs + qo*sn;
    float kn = kv*cs + ko*sn;
    float sq = (qn>0.f) ? qn+1.f : expf(qn);
    float sk = (kn>0.f) ? kn+1.f : expf(kn);
    __syncthreads();   // all reads of this row done before overwrite
    g_sq[base+d] = sq;
    g_sk[base+d] = sk;
    __nv_bfloat16 h,l;
    bf16split(qn,h,l); g_qH[base+d]=h;  g_qL[base+d]=l;
    bf16split(kn,h,l); g_kH[base+d]=h;  g_kL[base+d]=l;
    bf16split(sq,h,l); g_sqH[base+d]=h; g_sqL[base+d]=l;
}

// ---------------- den[row] = dot(sig_q[row], z[h]) ----------------
__global__ __launch_bounds__(256) void den_kernel(const float* __restrict__ z)
{
    int wid = threadIdx.x>>5, lane = threadIdx.x&31;
    int row = blockIdx.x*8 + wid;
    int h = (row>>11)&15;
    const float4* sq = (const float4*)(g_sq + (size_t)row*DD);
    const float4* zz = (const float4*)(z + h*DD);
    float4 a = sq[lane], b = zz[lane];
    float dot = a.x*b.x + a.y*b.y + a.z*b.z + a.w*b.w;
    #pragma unroll
    for (int o=16;o>0;o>>=1) dot += __shfl_down_sync(0xffffffffu, dot, o);
    if (lane==0) g_den[row] = dot;
}

// ---------------- memory retrieval via HMMA: (sig_q @ M[h]) / den ----------------
#define MR_TILE (128*136*2)   // bytes per bf16 tile
__global__ __launch_bounds__(256) void memret_mma_kernel()
{
    extern __shared__ char sm[];
    uint32_t sb = smem_u32(sm);
    float* denS = (float*)(sm + 4*MR_TILE);
    int s0 = blockIdx.x * 128;
    int bh = blockIdx.y;
    int h  = bh & 15;
    int t = threadIdx.x, wid=t>>5, lane=t&31;
    int wm = wid>>2, wn = wid&3;
    size_t rowbase = (size_t)bh*SS + s0;

    const uint4* srcs[4] = {
        (const uint4*)g_sqH + rowbase*16, (const uint4*)g_sqL + rowbase*16,
        (const uint4*)g_MtH + (size_t)h*2048, (const uint4*)g_MtL + (size_t)h*2048 };
    uint4* s4 = (uint4*)sm;
    #pragma unroll
    for (int i=0;i<32;i++){
        int slot = t + i*256;           // 8192
        int sp = slot>>11, r = (slot>>4)&127, c16 = slot&15;
        s4[sp*(MR_TILE/16) + r*17 + c16] = srcs[sp][(size_t)r*16 + c16];
    }
    if (t < 128) denS[t] = g_den[rowbase + t];
    __syncthreads();

    float acc[4][4][4];
    #pragma unroll
    for (int mt=0;mt<4;mt++)
        #pragma unroll
        for (int nt=0;nt<4;nt++)
            #pragma unroll
            for (int e=0;e<4;e++) acc[mt][nt][e]=0.f;

    uint32_t aRow = (uint32_t)(wm*64 + (lane&15));
    uint32_t aChk = (uint32_t)(lane>>4);
    uint32_t bRow = (uint32_t)(wn*32 + (lane&7));
    uint32_t bChk = (uint32_t)((lane>>3)&1);

    #pragma unroll
    for (int kf=0; kf<8; kf++){
        uint32_t aH[4][4], aL[4][4], bH[4][2], bL[4][2];
        #pragma unroll
        for (int mt=0;mt<4;mt++){
            uint32_t off = (aRow + mt*16)*272u + (kf*2 + aChk)*16u;
            ldsm_x4(aH[mt][0],aH[mt][1],aH[mt][2],aH[mt][3], sb + 0*MR_TILE + off);
            ldsm_x4(aL[mt][0],aL[mt][1],aL[mt][2],aL[mt][3], sb + 1*MR_TILE + off);
        }
        #pragma unroll
        for (int nt=0;nt<4;nt++){
            uint32_t off = (bRow + nt*8)*272u + (kf*2 + bChk)*16u;
            ldsm_x2(bH[nt][0],bH[nt][1], sb + 2*MR_TILE + off);
            ldsm_x2(bL[nt][0],bL[nt][1], sb + 3*MR_TILE + off);
        }
        #pragma unroll
        for (int mt=0;mt<4;mt++)
            #pragma unroll
            for (int nt=0;nt<4;nt++){
                mma_bf16(acc[mt][nt], aH[mt], bH[nt]);
                mma_bf16(acc[mt][nt], aH[mt], bL[nt]);
                mma_bf16(acc[mt][nt], aL[mt], bH[nt]);
            }
    }

    int rB = wm*64 + (lane>>2);
    int cB = wn*32 + (lane&3)*2;
    size_t obase = ((size_t)bh*SS + s0)*DD;
    #pragma unroll
    for (int mt=0;mt<4;mt++)
        #pragma unroll
        for (int nt=0;nt<4;nt++)
            #pragma unroll
            for (int half=0; half<2; half++){
                int row = rB + mt*16 + half*8;
                int col = cB + nt*8;
                float dinv = 1.f/denS[row];
                g_mem[obase + (size_t)row*DD + col]   = acc[mt][nt][half*2+0]*dinv;
                g_mem[obase + (size_t)row*DD + col+1] = acc[mt][nt][half*2+1]*dinv;
            }
}

// ---------------- flash attention via HMMA, split precision ----------------
#define FQ_H 0
#define FQ_L 34816
#define FK_H 69632
#define FK_L 87040
#define FVT_H 104448
#define FVT_L 122880
#define FPS 141312
#define FP_H 174592
#define FP_L 193024
#define FMR 211456
#define FSCR 212992
#define FTOT 215040

__global__ __launch_bounds__(256,1) void attn_mma_kernel()
{
    extern __shared__ char sm[];
    uint32_t sb = smem_u32(sm);
    float* PS   = (float*)(sm + FPS);
    __nv_bfloat16* PH  = (__nv_bfloat16*)(sm + FP_H);
    __nv_bfloat16* PL  = (__nv_bfloat16*)(sm + FP_L);
    float* mrow = (float*)(sm + FMR);
    float* lrow = mrow + 128;
    float* rs   = lrow + 128;
    float* scrA = (float*)(sm + FSCR);
    float* scrB = scrA + 256;

    int qb = 15 - blockIdx.x;   // longest causal tiles first
    int bh = blockIdx.y;
    int t = threadIdx.x, wid=t>>5, lane=t&31;
    int wm = wid>>2, wn = wid&3;
    size_t rowbase = (size_t)bh*SS;
    size_t base = rowbase*DD;

    // Q splits: 4096 uint4
    {
        uint4* s4 = (uint4*)sm;
        const uint4* q4[2] = { (const uint4*)g_qH + (rowbase + qb*128)*16,
                               (const uint4*)g_qL + (rowbase + qb*128)*16 };
        #pragma unroll
        for (int i=0;i<16;i++){
            int slot = t + i*256;
            int sp = slot>>11, r = (slot>>4)&127, c16 = slot&15;
            s4[(sp*34816)/16 + r*17 + c16] = q4[sp][(size_t)r*16 + c16];
        }
    }
    if (t < 128){ mrow[t] = -INFINITY; lrow[t] = 0.f; }

    float oacc[4][4][4];
    #pragma unroll
    for (int mt=0;mt<4;mt++)
        #pragma unroll
        for (int nt=0;nt<4;nt++)
            #pragma unroll
            for (int e=0;e<4;e++) oacc[mt][nt][e]=0.f;
    __syncthreads();

    const float sscale = 0.08838834764831845f;
    uint32_t aRow = (uint32_t)(wm*64 + (lane&15));
    uint32_t aChk = (uint32_t)(lane>>4);
    uint32_t bRowS = (uint32_t)(wn*16 + (lane&7));   // S phase: n-tile 16
    uint32_t bRowV = (uint32_t)(wn*32 + (lane&7));   // PV phase: n-tile 32
    uint32_t bChk = (uint32_t)((lane>>3)&1);
    int rB = wm*64 + (lane>>2);
    int srow = t>>1, shalf = t&1;

    int jbmax = 2*qb + 1;
    for (int jb=0; jb<=jbmax; jb++){
        // K tiles: 2048 uint4
        {
            uint4* s4 = (uint4*)(sm + FK_H);
            const uint4* k4[2] = { (const uint4*)g_kH + (rowbase + jb*64)*16,
                                   (const uint4*)g_kL + (rowbase + jb*64)*16 };
            #pragma unroll
            for (int i=0;i<8;i++){
                int slot = t + i*256;
                int sp = slot>>10, r = (slot>>4)&63, c16 = slot&15;
                s4[(sp*17408)/16 + r*17 + c16] = k4[sp][(size_t)r*16 + c16];
            }
        }
        // VT tiles from pre-split transposed V: 2048 uint4
        #pragma unroll
        for (int i=0;i<8;i++){
            int slot = t + i*256;
            int sp = slot>>10, r = (slot>>3)&127, c = slot&7;
            const __nv_bfloat16* src = sp ? g_vTL : g_vTH;
            uint4 v = *(const uint4*)(src + (size_t)(bh*128+r)*2048 + jb*64 + c*8);
            *(uint4*)(sm + FVT_H + sp*18432 + r*144 + c*16) = v;
        }
        __syncthreads();

        // S = Q K^T (3-pass)
        float sacc[4][2][4];
        #pragma unroll
        for (int mt=0;mt<4;mt++)
            #pragma unroll
            for (int nt=0;nt<2;nt++)
                #pragma unroll
                for (int e=0;e<4;e++) sacc[mt][nt][e]=0.f;
        #pragma unroll
        for (int kf=0; kf<8; kf++){
            uint32_t aH[4][4], aL[4][4], bH[2][2], bL[2][2];
            #pragma unroll
            for (int mt=0;mt<4;mt++){
                uint32_t off = (aRow + mt*16)*272u + (kf*2 + aChk)*16u;
                ldsm_x4(aH[mt][0],aH[mt][1],aH[mt][2],aH[mt][3], sb + FQ_H + off);
                ldsm_x4(aL[mt][0],aL[mt][1],aL[mt][2],aL[mt][3], sb + FQ_L + off);
            }
            #pragma unroll
            for (int nt=0;nt<2;nt++){
                uint32_t off = (bRowS + nt*8)*272u + (kf*2 + bChk)*16u;
                ldsm_x2(bH[nt][0],bH[nt][1], sb + FK_H + off);
                ldsm_x2(bL[nt][0],bL[nt][1], sb + FK_L + off);
            }
            #pragma unroll
            for (int mt=0;mt<4;mt++)
                #pragma unroll
                for (int nt=0;nt<2;nt++){
                    mma_bf16(sacc[mt][nt], aH[mt], bH[nt]);
                    mma_bf16(sacc[mt][nt], aH[mt], bL[nt]);
                    mma_bf16(sacc[mt][nt], aL[mt], bH[nt]);
                }
        }
        // store S -> PS with mask & scale
        {
            int cBs = wn*16 + (lane&3)*2;
            #pragma unroll
            for (int mt=0;mt<4;mt++)
                #pragma unroll
                for (int nt=0;nt<2;nt++)
                    #pragma unroll
                    for (int half=0; half<2; half++){
                        int row = rB + mt*16 + half*8;
                        int col = cBs + nt*8;
                        int qrow = qb*128 + row, kcol = jb*64 + col;
                        PS[row*65+col]   = (kcol   <= qrow) ? sacc[mt][nt][half*2+0]*sscale : -INFINITY;
                        PS[row*65+col+1] = (kcol+1 <= qrow) ? sacc[mt][nt][half*2+1]*sscale : -INFINITY;
                    }
        }
        __syncthreads();

        // online softmax: 2 threads per row (each 32 cols), two-phase
        {
            float* PSrow = PS + srow*65 + shalf*32;
            float pm = -INFINITY;
            #pragma unroll 8
            for (int j=0;j<32;j++) pm = fmaxf(pm, PSrow[j]);
            scrA[t] = pm;
            __syncthreads();
            float m_new = fmaxf(mrow[srow], fmaxf(scrA[2*srow], scrA[2*srow+1]));
            float psum = 0.f;
            #pragma unroll 8
            for (int j=0;j<32;j++){
                float p = __expf(PSrow[j] - m_new);
                PSrow[j] = p;
                psum += p;
            }
            scrB[t] = psum;
            __syncthreads();
            if (t < 128){
                float mo = mrow[t];
                float mn = fmaxf(mo, fmaxf(scrA[2*t], scrA[2*t+1]));
                float sc = __expf(mo - mn);
                lrow[t] = sc*lrow[t] + scrB[2*t] + scrB[2*t+1];
                mrow[t] = mn;
                rs[t]   = sc;
            }
        }
        __syncthreads();

        // split P -> bf16 (stride 72)
        #pragma unroll
        for (int i=0;i<32;i++){
            int e = i*256 + t;
            int row = e>>6, col = e&63;
            __nv_bfloat16 h,l; bf16split(PS[row*65+col], h, l);
            PH[row*72+col] = h; PL[row*72+col] = l;
        }
        __syncthreads();

        // rescale O, then O += P V (3-pass)
        #pragma unroll
        for (int mt=0;mt<4;mt++){
            float s0 = rs[rB + mt*16], s1 = rs[rB + mt*16 + 8];
            #pragma unroll
            for (int nt=0;nt<4;nt++){
                oacc[mt][nt][0] *= s0; oacc[mt][nt][1] *= s0;
                oacc[mt][nt][2] *= s1; oacc[mt][nt][3] *= s1;
            }
        }
        #pragma unroll
        for (int kf=0; kf<4; kf++){
            uint32_t aH[4][4], aL[4][4], bH[4][2], bL[4][2];
            #pragma unroll
            for (int mt=0;mt<4;mt++){
                uint32_t off = (aRow + mt*16)*144u + (kf*2 + aChk)*16u;
                ldsm_x4(aH[mt][0],aH[mt][1],aH[mt][2],aH[mt][3], sb + FP_H + off);
                ldsm_x4(aL[mt][0],aL[mt][1],aL[mt][2],aL[mt][3], sb + FP_L + off);
            }
            #pragma unroll
            for (int nt=0;nt<4;nt++){
                uint32_t off = (bRowV + nt*8)*144u + (kf*2 + bChk)*16u;
                ldsm_x2(bH[nt][0],bH[nt][1], sb + FVT_H + off);
                ldsm_x2(bL[nt][0],bL[nt][1], sb + FVT_L + off);
            }
            #pragma unroll
            for (int mt=0;mt<4;mt++)
                #pragma unroll
                for (int nt=0;nt<4;nt++){
                    mma_bf16(oacc[mt][nt], aH[mt], bH[nt]);
                    mma_bf16(oacc[mt][nt], aH[mt], bL[nt]);
                    mma_bf16(oacc[mt][nt], aL[mt], bH[nt]);
                }
        }
        __syncthreads();
    }

    // final normalize + store
    int cB = wn*32 + (lane&3)*2;
    #pragma unroll
    for (int mt=0;mt<4;mt++)
        #pragma unroll
        for (int half=0; half<2; half++){
            int row = rB + mt*16 + half*8;
            float linv = 1.f/lrow[row];
            #pragma unroll
            for (int nt=0;nt<4;nt++){
                int col = cB + nt*8;
                size_t o = base + (size_t)(qb*128+row)*DD + col;
                g_att[o]   = oacc[mt][nt][half*2+0]*linv;
                g_att[o+1] = oacc[mt][nt][half*2+1]*linv;
            }
        }
}

// ---------------- M update via HMMA: partials per (h, 256-row chunk) ----------------
__global__ __launch_bounds__(256) void m_update_mma_kernel()
{
    __shared__ __nv_bfloat16 skTH[128*40], skTL[128*40], vTH[128*40], vTL[128*40];
    __shared__ float zred[256];
    uint32_t sA_H = smem_u32(skTH), sA_L = smem_u32(skTL);
    uint32_t sB_H = smem_u32(vTH),  sB_L = smem_u32(vTL);

    int h = blockIdx.x, c = blockIdx.y;
    int b = c>>3, s0 = (c&7)*256;
    size_t base = (((size_t)(b*HH + h))*SS + s0)*DD;
    int t = threadIdx.x, wid=t>>5, lane=t&31;
    int wm = wid>>2, wn = wid&3;

    float acc[4][4][4];
    #pragma unroll
    for (int mt=0;mt<4;mt++)
        #pragma unroll
        for (int nt=0;nt<4;nt++)
            #pragma unroll
            for (int e=0;e<4;e++) acc[mt][nt][e]=0.f;
    float zacc = 0.f;

    uint32_t aRow = (uint32_t)(wm*64 + (lane&15));
    uint32_t aChk = (uint32_t)(lane>>4);
    uint32_t bRow = (uint32_t)(wn*32 + (lane&7));
    uint32_t bChk = (uint32_t)((lane>>3)&1);

    for (int kc=0; kc<8; kc++){
        // transpose+split 32x128 chunks of sk and v
        #pragma unroll
        for (int i=0;i<16;i++){
            int e = i*256 + t;
            int s = e>>7, d = e&127;
            size_t g = base + (size_t)(kc*32+s)*DD + d;
            float sv = g_sk[g], vv = g_v[g];
            __nv_bfloat16 hh,ll;
            bf16split(sv,hh,ll); skTH[d*40+s]=hh; skTL[d*40+s]=ll;
            bf16split(vv,hh,ll); vTH[d*40+s]=hh;  vTL[d*40+s]=ll;
            zacc += sv;   // d = t&127, invariant per thread
        }
        __syncthreads();

        #pragma unroll
        for (int kf=0; kf<2; kf++){
            uint32_t aH[4][4], aL[4][4], bH[4][2], bL[4][2];
            #pragma unroll
            for (int mt=0;mt<4;mt++){
                uint32_t off = (aRow + mt*16)*80u + (kf*2 + aChk)*16u;
                ldsm_x4(aH[mt][0],aH[mt][1],aH[mt][2],aH[mt][3], sA_H + off);
                ldsm_x4(aL[mt][0],aL[mt][1],aL[mt][2],aL[mt][3], sA_L + off);
            }
            #pragma unroll
            for (int nt=0;nt<4;nt++){
                uint32_t off = (bRow + nt*8)*80u + (kf*2 + bChk)*16u;
                ldsm_x2(bH[nt][0],bH[nt][1], sB_H + off);
                ldsm_x2(bL[nt][0],bL[nt][1], sB_L + off);
            }
            #pragma unroll
            for (int mt=0;mt<4;mt++)
                #pragma unroll
                for (int nt=0;nt<4;nt++){
                    mma_bf16(acc[mt][nt], aH[mt], bH[nt]);
                    mma_bf16(acc[mt][nt], aH[mt], bL[nt]);
                    mma_bf16(acc[mt][nt], aL[mt], bH[nt]);
                }
        }
        __syncthreads();
    }

    zred[t] = zacc;
    __syncthreads();
    if (t < 128) g_zpart[(h*16 + c)*DD + t] = zred[t] + zred[t+128];

    size_t pbase = ((size_t)(h*16 + c)) << 14;
    int rB = wm*64 + (lane>>2);
    int cB = wn*32 + (lane&3)*2;
    #pragma unroll
    for (int mt=0;mt<4;mt++)
        #pragma unroll
        for (int nt=0;nt<4;nt++)
            #pragma unroll
            for (int half=0; half<2; half++){
                int row = rB + mt*16 + half*8;   // d
                int col = cB + nt*8;              // e
                g_mpart[pbase + (size_t)row*DD + col]   = acc[mt][nt][half*2+0];
                g_mpart[pbase + (size_t)row*DD + col+1] = acc[mt][nt][half*2+1];
            }
}

__global__ void reduce_m_kernel(const float* __restrict__ M, float* __restrict__ out)
{
    int idx = blockIdx.x*256 + threadIdx.x;
    int h = idx >> 14;
    int de = idx & 16383;
    float s = M[idx];
    #pragma unroll
    for (int c=0;c<16;c++) s += g_mpart[(((size_t)(h*16+c))<<14) + de];
    out[idx] = s;
}

__global__ void reduce_z_kernel(const float* __restrict__ z, float* __restrict__ out)
{
    int idx = blockIdx.x*256 + threadIdx.x;
    float s = z[idx];
    int h = idx >> 7, d = idx & 127;
    #pragma unroll
    for (int c=0;c<16;c++) s += g_zpart[(h*16+c)*DD + d];
    out[idx] = s;
}

// ---------------- launch ----------------
extern "C" void kernel_launch(void* const* d_in, const int* in_sizes, int n_in,
                              void* d_out, int out_size)
{
    (void)in_sizes; (void)n_in; (void)out_size;
    const float* hs   = (const float*)d_in[0];
    const float* Wq   = (const float*)d_in[1];
    const float* bq   = (const float*)d_in[2];
    const float* Wk   = (const float*)d_in[3];
    const float* bk   = (const float*)d_in[4];
    const float* Wv   = (const float*)d_in[5];
    const float* bv   = (const float*)d_in[6];
    const float* Wo   = (const float*)d_in[7];
    const float* beta = (const float*)d_in[8];
    const float* Mm   = (const float*)d_in[9];
    const float* zz   = (const float*)d_in[10];
    const int* pos    = (const int*)d_in[12];
    float* out = (float*)d_out;

    cudaFuncSetAttribute(attn_mma_kernel, cudaFuncAttributeMaxDynamicSharedMemorySize, FTOT);
    cudaFuncSetAttribute(memret_mma_kernel, cudaFuncAttributeMaxDynamicSharedMemorySize, 4*MR_TILE + 512);
    cudaFuncSetAttribute(gemm_mma_kernel, cudaFuncAttributeMaxDynamicSharedMemorySize, GEMM_SMEM);
    cudaFuncSetAttribute(vsplitT_kernel, cudaFuncAttributeMaxDynamicSharedMemorySize, VT_SMEM);

    // splits + transposes of inputs
    split_a_kernel<<<MTOT*HIDN/256, 256>>>(hs);
    wsplit_kernel<<<dim3(64,64,4), 256>>>(Wq, Wk, Wv, Wo);
    msplit_kernel<<<1024, 256>>>(Mm);

    // QKV (q->g_sq staging, k->g_sk staging, v->g_v)
    gemm_mma_kernel<<<dim3(16,32,3), 256, GEMM_SMEM>>>(bq, bk, bv, nullptr, 0);

    // rope: consumes staged q/k, emits bf16 splits + sigma
    rope_kernel<<<BHS/2, 256>>>(pos);

    // V transpose+split for attention PV
    vsplitT_kernel<<<dim3(32,16), 256, VT_SMEM>>>();

    den_kernel<<<BHS/8, 256>>>(zz);
    memret_mma_kernel<<<dim3(16,32), 256, 4*MR_TILE + 512>>>();

    attn_mma_kernel<<<dim3(16,32), 256, FTOT>>>();

    m_update_mma_kernel<<<dim3(16,16), 256>>>();
    reduce_m_kernel<<<1024, 256>>>(Mm, out + 8388608);
    reduce_z_kernel<<<8, 256>>>(zz, out + 8388608 + 262144);

    combine_split_kernel<<<MTOT*HIDN/256, 256>>>(beta);
    gemm_mma_kernel<<<dim3(16,32,1), 256, GEMM_SMEM>>>(bq, bk, bv, out, 1);
}

// round 13
// speedup vs baseline: 2.7765x; 1.0541x over previous
#include <cuda_runtime.h>
#include <cuda_bf16.h>
#include <math.h>
#include <stdint.h>

#define BB 2
#define SS 2048
#define HH 16
#define DD 128
#define HIDN 2048
#define BHS (BB*HH*SS)          // 65536 rows of length D
#define MTOT 4096               // B*S rows

// ---------------- scratch (static device globals; no allocation) ----------------
__device__ float g_v  [BB*HH*SS*DD];
__device__ float g_sq [BB*HH*SS*DD];
__device__ float g_sk [BB*HH*SS*DD];
__device__ float g_mem[BB*HH*SS*DD];
__device__ float g_att[BB*HH*SS*DD];
__device__ float g_den[BHS];
__device__ float g_mpart[HH*16*DD*DD];
__device__ float g_zpart[HH*16*DD];

// bf16 split-precision operands
__device__ __nv_bfloat16 g_AH[MTOT*HIDN];
__device__ __nv_bfloat16 g_AL[MTOT*HIDN];
__device__ __nv_bfloat16 g_WtH[4u*HIDN*HIDN];   // [which][n][k] transposed
__device__ __nv_bfloat16 g_WtL[4u*HIDN*HIDN];
__device__ __nv_bfloat16 g_CH[MTOT*HIDN];       // gated combine, split
__device__ __nv_bfloat16 g_CL[MTOT*HIDN];
__device__ __nv_bfloat16 g_qH[BB*HH*SS*DD];     // post-rope q/k splits
__device__ __nv_bfloat16 g_qL[BB*HH*SS*DD];
__device__ __nv_bfloat16 g_kH[BB*HH*SS*DD];
__device__ __nv_bfloat16 g_kL[BB*HH*SS*DD];
__device__ __nv_bfloat16 g_sqH[BB*HH*SS*DD];    // sigma(q) splits
__device__ __nv_bfloat16 g_sqL[BB*HH*SS*DD];
__device__ __nv_bfloat16 g_MtH[HH*DD*DD];       // M transposed [h][e][d] splits
__device__ __nv_bfloat16 g_MtL[HH*DD*DD];
__device__ __nv_bfloat16 g_vTH[BB*HH*SS*DD];    // V transposed [bh][d][s] splits
__device__ __nv_bfloat16 g_vTL[BB*HH*SS*DD];

// ================= mma.sync helpers (validated round 6) =================
__device__ __forceinline__ uint32_t smem_u32(const void* p){
    return (uint32_t)__cvta_generic_to_shared(p);
}
__device__ __forceinline__ void ldsm_x4(uint32_t& r0, uint32_t& r1, uint32_t& r2, uint32_t& r3, uint32_t addr){
    asm volatile("ldmatrix.sync.aligned.m8n8.x4.shared.b16 {%0,%1,%2,%3}, [%4];"
        : "=r"(r0), "=r"(r1), "=r"(r2), "=r"(r3) : "r"(addr));
}
__device__ __forceinline__ void ldsm_x2(uint32_t& r0, uint32_t& r1, uint32_t addr){
    asm volatile("ldmatrix.sync.aligned.m8n8.x2.shared.b16 {%0,%1}, [%2];"
        : "=r"(r0), "=r"(r1) : "r"(addr));
}
__device__ __forceinline__ void mma_bf16(float* d, const uint32_t* a, const uint32_t* b){
    asm volatile("mma.sync.aligned.m16n8k16.row.col.f32.bf16.bf16.f32 "
        "{%0,%1,%2,%3}, {%4,%5,%6,%7}, {%8,%9}, {%0,%1,%2,%3};"
        : "+f"(d[0]), "+f"(d[1]), "+f"(d[2]), "+f"(d[3])
        : "r"(a[0]), "r"(a[1]), "r"(a[2]), "r"(a[3]), "r"(b[0]), "r"(b[1]));
}
__device__ __forceinline__ void bf16split(float v, __nv_bfloat16& h, __nv_bfloat16& l){
    h = __float2bfloat16_rn(v);
    l = __float2bfloat16_rn(v - __bfloat162float(h));
}
__device__ __forceinline__ void cp_async16(uint32_t smem_addr, const void* gptr){
    asm volatile("cp.async.cg.shared.global [%0], [%1], 16;" :: "r"(smem_addr), "l"(gptr));
}
#define CP_COMMIT() asm volatile("cp.async.commit_group;" ::: "memory")
#define CP_WAIT1()  asm volatile("cp.async.wait_group 1;" ::: "memory")
#define CP_WAIT0()  asm volatile("cp.async.wait_group 0;" ::: "memory")

// ================= pre-pass kernels =================
__global__ __launch_bounds__(256) void split_a_kernel(const float* __restrict__ A)
{
    int idx = blockIdx.x*256 + threadIdx.x;
    __nv_bfloat16 h,l; bf16split(A[idx], h, l);
    g_AH[idx] = h; g_AL[idx] = l;
}

__global__ __launch_bounds__(256) void wsplit_kernel(
    const float* __restrict__ Wq, const float* __restrict__ Wk,
    const float* __restrict__ Wv, const float* __restrict__ Wo)
{
    __shared__ float tile[32][33];
    int z = blockIdx.z;
    const float* W = (z==0)?Wq:((z==1)?Wk:((z==2)?Wv:Wo));
    __nv_bfloat16* H = g_WtH + (size_t)z*HIDN*HIDN;
    __nv_bfloat16* L = g_WtL + (size_t)z*HIDN*HIDN;
    int n0 = blockIdx.x*32, k0 = blockIdx.y*32;
    int tx = threadIdx.x & 31, ty = threadIdx.x >> 5;
    #pragma unroll
    for (int i=0;i<4;i++)
        tile[ty+8*i][tx] = W[(size_t)(k0+ty+8*i)*HIDN + n0+tx];
    __syncthreads();
    #pragma unroll
    for (int i=0;i<4;i++){
        __nv_bfloat16 h,l; bf16split(tile[tx][ty+8*i], h, l);
        size_t o = (size_t)(n0+ty+8*i)*HIDN + k0+tx;
        H[o] = h; L[o] = l;
    }
}

// transpose+split M: src [h][d][e] -> dst [h][e][d]
__global__ __launch_bounds__(256) void msplit_kernel(const float* __restrict__ M)
{
    int idx = blockIdx.x*256 + threadIdx.x;   // 262144
    int h = idx >> 14, d = (idx>>7)&127, e = idx&127;
    __nv_bfloat16 hh,ll; bf16split(M[idx], hh, ll);
    size_t o = (size_t)h*16384 + e*128 + d;
    g_MtH[o] = hh; g_MtL[o] = ll;
}

__global__ __launch_bounds__(256) void combine_split_kernel(const float* __restrict__ beta)
{
    int idx = blockIdx.x*256 + threadIdx.x;
    float g = 1.f/(1.f + expf(-beta[0]));
    int m = idx >> 11, kcol = idx & 2047;
    int b = m>>11, s = m&2047, h = kcol>>7, d = kcol&127;
    size_t a = (((size_t)(b*HH+h))*SS + s)*DD + d;
    float v = g*g_mem[a] + (1.f-g)*g_att[a];
    __nv_bfloat16 hh,ll; bf16split(v, hh, ll);
    g_CH[idx] = hh; g_CL[idx] = ll;
}

// transpose+split V: [bh][s][d] fp32 -> [bh][d][s] bf16 H/L.
#define VT_SMEM (2*128*66*4)
__global__ __launch_bounds__(256) void vsplitT_kernel()
{
    extern __shared__ char sm[];
    uint32_t* sH = (uint32_t*)sm;            // [128 d][66]
    uint32_t* sL = sH + 128*66;
    int bh = blockIdx.x, sc0 = blockIdx.y*128;
    int t = threadIdx.x;
    size_t base = ((size_t)bh*SS + sc0)*DD;
    #pragma unroll
    for (int i=0;i<32;i++){
        int pidx = i*256 + t;      // 8192 pairs
        int d = pidx & 127, sp = pidx >> 7;   // sp 0..63
        float v0 = g_v[base + (size_t)(2*sp)*DD + d];
        float v1 = g_v[base + (size_t)(2*sp+1)*DD + d];
        __nv_bfloat16 h0,l0,h1,l1;
        bf16split(v0,h0,l0); bf16split(v1,h1,l1);
        uint32_t ph = ((uint32_t)__bfloat16_as_ushort(h1)<<16) | (uint32_t)__bfloat16_as_ushort(h0);
        uint32_t pl = ((uint32_t)__bfloat16_as_ushort(l1)<<16) | (uint32_t)__bfloat16_as_ushort(l0);
        sH[d*66 + sp] = ph;
        sL[d*66 + sp] = pl;
    }
    __syncthreads();
    #pragma unroll
    for (int i=0;i<16;i++){
        int flat = i*256 + t;      // 4096 = 128 d x 32 c2
        int d = flat>>5, c2 = flat&31;
        uint2 vh = *(uint2*)&sH[d*66 + c2*2];
        uint2 vl = *(uint2*)&sL[d*66 + c2*2];
        size_t o32 = ((size_t)(bh*128+d)*2048 + sc0)/2 + c2*2;
        *(uint2*)((uint32_t*)g_vTH + o32) = vh;
        *(uint2*)((uint32_t*)g_vTL + o32) = vl;
    }
}

// ================= HMMA GEMM: cp.async pipeline, 2 CTAs/SM =================
#define TSTRIDE 40
#define TILE_BF16 (128*TSTRIDE)
#define TILE_U4   (TILE_BF16/8)
#define BUF_BYTES (4*TILE_BF16*2)      // 40960 per stage
#define GEMM_SMEM (2*BUF_BYTES)        // 81920

__global__ __launch_bounds__(256,2) void gemm_mma_kernel(
    const float* __restrict__ bq, const float* __restrict__ bk, const float* __restrict__ bv,
    float* __restrict__ outp, int asel)
{
    extern __shared__ char sm[];
    uint32_t sbase = smem_u32(sm);

    int t = threadIdx.x;
    int wid = t>>5, lane = t&31;
    int wm = wid>>2, wn = wid&3;
    int n0 = blockIdx.x*128;
    int m0 = blockIdx.y*128;
    int which = (asel==0) ? blockIdx.z : 3;
    const __nv_bfloat16* Ah = (asel==0) ? g_AH : g_CH;
    const __nv_bfloat16* Al = (asel==0) ? g_AL : g_CL;
    const __nv_bfloat16* Bh = g_WtH + (size_t)which*HIDN*HIDN;
    const __nv_bfloat16* Bl = g_WtL + (size_t)which*HIDN*HIDN;

    const __nv_bfloat16* gsrc[4] = {
        Ah + (size_t)m0*HIDN, Al + (size_t)m0*HIDN,
        Bh + (size_t)n0*HIDN, Bl + (size_t)n0*HIDN };

    // per-thread 8 load slots: global base pointer + smem byte offset within a stage
    const __nv_bfloat16* gp[8];
    uint32_t soff[8];
    #pragma unroll
    for (int i=0;i<8;i++){
        int slot = t + i*256;
        int tt = slot>>9;
        int w = slot&511;
        int rr = w>>2, cc = w&3;
        gp[i] = gsrc[tt] + (size_t)rr*HIDN + cc*8;
        soff[i] = (uint32_t)(tt*TILE_U4 + rr*5 + cc)*16u;
    }

    float acc[4][4][4];
    #pragma unroll
    for (int mt=0;mt<4;mt++)
        #pragma unroll
        for (int nt=0;nt<4;nt++)
            #pragma unroll
            for (int e=0;e<4;e++) acc[mt][nt][e] = 0.f;

    uint32_t aRow = (uint32_t)(wm*64 + (lane&15));
    uint32_t aChk = (uint32_t)(lane>>4);
    uint32_t bRow = (uint32_t)(wn*32 + (lane&7));
    uint32_t bChk = (uint32_t)((lane>>3)&1);

    // prologue: chunks 0,1 in flight
    #pragma unroll
    for (int i=0;i<8;i++) cp_async16(sbase + soff[i], gp[i]);
    CP_COMMIT();
    #pragma unroll
    for (int i=0;i<8;i++) cp_async16(sbase + BUF_BYTES + soff[i], gp[i] + 32);
    CP_COMMIT();

    for (int kt=0; kt<64; kt++){
        int cur = kt & 1;
        if (kt == 63) { CP_WAIT0(); } else { CP_WAIT1(); }
        __syncthreads();

        uint32_t bufb = sbase + (uint32_t)cur*BUF_BYTES;
        #pragma unroll
        for (int k16=0;k16<2;k16++){
            uint32_t aH[4][4], aL[4][4], bH[4][2], bL[4][2];
            #pragma unroll
            for (int mt=0;mt<4;mt++){
                uint32_t off = (aRow + mt*16)*80u + (k16*2 + aChk)*16u;
                ldsm_x4(aH[mt][0],aH[mt][1],aH[mt][2],aH[mt][3], bufb + 0*TILE_BF16*2 + off);
                ldsm_x4(aL[mt][0],aL[mt][1],aL[mt][2],aL[mt][3], bufb + 1*TILE_BF16*2 + off);
            }
            #pragma unroll
            for (int nt=0;nt<4;nt++){
                uint32_t off = (bRow + nt*8)*80u + (k16*2 + bChk)*16u;
                ldsm_x2(bH[nt][0],bH[nt][1], bufb + 2*TILE_BF16*2 + off);
                ldsm_x2(bL[nt][0],bL[nt][1], bufb + 3*TILE_BF16*2 + off);
            }
            #pragma unroll
            for (int mt=0;mt<4;mt++)
                #pragma unroll
                for (int nt=0;nt<4;nt++){
                    mma_bf16(acc[mt][nt], aH[mt], bH[nt]);
                    mma_bf16(acc[mt][nt], aH[mt], bL[nt]);
                    mma_bf16(acc[mt][nt], aL[mt], bH[nt]);
                }
        }

        // refill the buffer we just finished with chunk kt+2
        if (kt < 62){
            __syncthreads();
            int k0 = (kt+2)*32;
            #pragma unroll
            for (int i=0;i<8;i++) cp_async16(sbase + (uint32_t)cur*BUF_BYTES + soff[i], gp[i] + k0);
            CP_COMMIT();
        }
    }

    int rB = wm*64 + (lane>>2);
    int cB = wn*32 + (lane&3)*2;
    if (asel == 0){
        const float* bias = (which==0)?bq:((which==1)?bk:bv);
        int h = n0>>7;
        #pragma unroll
        for (int mt=0;mt<4;mt++){
            #pragma unroll
            for (int nt=0;nt<4;nt++){
                int row = rB + mt*16;
                int col = cB + nt*8;
                int n = n0 + col;
                #pragma unroll
                for (int half=0; half<2; half++){
                    int m = m0 + row + half*8;
                    int b = m>>11, s = m&2047;
                    size_t o = (((size_t)(b*HH+h))*SS + s)*DD + col;
                    float v0 = acc[mt][nt][half*2+0] + bias[n];
                    float v1 = acc[mt][nt][half*2+1] + bias[n+1];
                    if (which == 2){            // V: fp32
                        g_v[o] = v0; g_v[o+1] = v1;
                    } else {                     // Q/K staging pre-rope
                        float* O = (which==0)?g_sq:g_sk;
                        O[o] = v0; O[o+1] = v1;
                    }
                }
            }
        }
    } else {
        #pragma unroll
        for (int mt=0;mt<4;mt++){
            #pragma unroll
            for (int nt=0;nt<4;nt++){
                int row = rB + mt*16;
                int col = cB + nt*8;
                #pragma unroll
                for (int half=0; half<2; half++){
                    size_t o = (size_t)(m0 + row + half*8)*HIDN + n0 + col;
                    outp[o]   = acc[mt][nt][half*2+0];
                    outp[o+1] = acc[mt][nt][half*2+1];
                }
            }
        }
    }
}

// ---------------- RoPE + sigma; reads staged q/k (g_sq/g_sk raw), writes splits ----------------
__global__ __launch_bounds__(256) void rope_kernel(const int* __restrict__ pos)
{
    int t = threadIdx.x;
    long rid = (long)blockIdx.x*2 + (t>>7);
    int d = t & 127;
    int s  = (int)(rid & (SS-1));
    int bh = (int)(rid >> 11);
    int b  = bh >> 4;
    size_t base = (size_t)rid * DD;
    float qv = g_sq[base+d], kv = g_sk[base+d];
    float qo = (d<64)? -g_sq[base+d+64] : g_sq[base+d-64];
    float ko = (d<64)? -g_sk[base+d+64] : g_sk[base+d-64];
    int p = pos[(size_t)b*SS + s];
    float inv = expf(-0.14391156831212787f * (float)(d & 63));
    float ang = (float)p * inv;
    float sn, cs;
    sincosf(ang, &sn, &cs);
    float qn = qv*cs + qo*sn;
    float kn = kv*cs + ko*sn;
    float sq = (qn>0.f) ? qn+1.f : expf(qn);
    float sk = (kn>0.f) ? kn+1.f : expf(kn);
    __syncthreads();   // all reads of this row done before overwrite
    g_sq[base+d] = sq;
    g_sk[base+d] = sk;
    __nv_bfloat16 h,l;
    bf16split(qn,h,l); g_qH[base+d]=h;  g_qL[base+d]=l;
    bf16split(kn,h,l); g_kH[base+d]=h;  g_kL[base+d]=l;
    bf16split(sq,h,l); g_sqH[base+d]=h; g_sqL[base+d]=l;
}

// ---------------- den[row] = dot(sig_q[row], z[h]) ----------------
__global__ __launch_bounds__(256) void den_kernel(const float* __restrict__ z)
{
    int wid = threadIdx.x>>5, lane = threadIdx.x&31;
    int row = blockIdx.x*8 + wid;
    int h = (row>>11)&15;
    const float4* sq = (const float4*)(g_sq + (size_t)row*DD);
    const float4* zz = (const float4*)(z + h*DD);
    float4 a = sq[lane], b = zz[lane];
    float dot = a.x*b.x + a.y*b.y + a.z*b.z + a.w*b.w;
    #pragma unroll
    for (int o=16;o>0;o>>=1) dot += __shfl_down_sync(0xffffffffu, dot, o);
    if (lane==0) g_den[row] = dot;
}

// ---------------- memory retrieval via HMMA: (sig_q @ M[h]) / den ----------------
#define MR_TILE (128*136*2)   // bytes per bf16 tile
__global__ __launch_bounds__(256) void memret_mma_kernel()
{
    extern __shared__ char sm[];
    uint32_t sb = smem_u32(sm);
    float* denS = (float*)(sm + 4*MR_TILE);
    int s0 = blockIdx.x * 128;
    int bh = blockIdx.y;
    int h  = bh & 15;
    int t = threadIdx.x, wid=t>>5, lane=t&31;
    int wm = wid>>2, wn = wid&3;
    size_t rowbase = (size_t)bh*SS + s0;

    const uint4* srcs[4] = {
        (const uint4*)g_sqH + rowbase*16, (const uint4*)g_sqL + rowbase*16,
        (const uint4*)g_MtH + (size_t)h*2048, (const uint4*)g_MtL + (size_t)h*2048 };
    uint4* s4 = (uint4*)sm;
    #pragma unroll
    for (int i=0;i<32;i++){
        int slot = t + i*256;           // 8192
        int sp = slot>>11, r = (slot>>4)&127, c16 = slot&15;
        s4[sp*(MR_TILE/16) + r*17 + c16] = srcs[sp][(size_t)r*16 + c16];
    }
    if (t < 128) denS[t] = g_den[rowbase + t];
    __syncthreads();

    float acc[4][4][4];
    #pragma unroll
    for (int mt=0;mt<4;mt++)
        #pragma unroll
        for (int nt=0;nt<4;nt++)
            #pragma unroll
            for (int e=0;e<4;e++) acc[mt][nt][e]=0.f;

    uint32_t aRow = (uint32_t)(wm*64 + (lane&15));
    uint32_t aChk = (uint32_t)(lane>>4);
    uint32_t bRow = (uint32_t)(wn*32 + (lane&7));
    uint32_t bChk = (uint32_t)((lane>>3)&1);

    #pragma unroll
    for (int kf=0; kf<8; kf++){
        uint32_t aH[4][4], aL[4][4], bH[4][2], bL[4][2];
        #pragma unroll
        for (int mt=0;mt<4;mt++){
            uint32_t off = (aRow + mt*16)*272u + (kf*2 + aChk)*16u;
            ldsm_x4(aH[mt][0],aH[mt][1],aH[mt][2],aH[mt][3], sb + 0*MR_TILE + off);
            ldsm_x4(aL[mt][0],aL[mt][1],aL[mt][2],aL[mt][3], sb + 1*MR_TILE + off);
        }
        #pragma unroll
        for (int nt=0;nt<4;nt++){
            uint32_t off = (bRow + nt*8)*272u + (kf*2 + bChk)*16u;
            ldsm_x2(bH[nt][0],bH[nt][1], sb + 2*MR_TILE + off);
            ldsm_x2(bL[nt][0],bL[nt][1], sb + 3*MR_TILE + off);
        }
        #pragma unroll
        for (int mt=0;mt<4;mt++)
            #pragma unroll
            for (int nt=0;nt<4;nt++){
                mma_bf16(acc[mt][nt], aH[mt], bH[nt]);
                mma_bf16(acc[mt][nt], aH[mt], bL[nt]);
                mma_bf16(acc[mt][nt], aL[mt], bH[nt]);
            }
    }

    int rB = wm*64 + (lane>>2);
    int cB = wn*32 + (lane&3)*2;
    size_t obase = ((size_t)bh*SS + s0)*DD;
    #pragma unroll
    for (int mt=0;mt<4;mt++)
        #pragma unroll
        for (int nt=0;nt<4;nt++)
            #pragma unroll
            for (int half=0; half<2; half++){
                int row = rB + mt*16 + half*8;
                int col = cB + nt*8;
                float dinv = 1.f/denS[row];
                g_mem[obase + (size_t)row*DD + col]   = acc[mt][nt][half*2+0]*dinv;
                g_mem[obase + (size_t)row*DD + col+1] = acc[mt][nt][half*2+1]*dinv;
            }
}

// ---------------- flash attention via HMMA, split precision ----------------
#define FQ_H 0
#define FQ_L 34816
#define FK_H 69632
#define FK_L 87040
#define FVT_H 104448
#define FVT_L 122880
#define FPS 141312
#define FP_H 174592
#define FP_L 193024
#define FMR 211456
#define FSCR 212992
#define FTOT 215040

__global__ __launch_bounds__(256,1) void attn_mma_kernel()
{
    extern __shared__ char sm[];
    uint32_t sb = smem_u32(sm);
    float* PS   = (float*)(sm + FPS);
    __nv_bfloat16* PH  = (__nv_bfloat16*)(sm + FP_H);
    __nv_bfloat16* PL  = (__nv_bfloat16*)(sm + FP_L);
    float* mrow = (float*)(sm + FMR);
    float* lrow = mrow + 128;
    float* rs   = lrow + 128;
    float* scrA = (float*)(sm + FSCR);
    float* scrB = scrA + 256;

    int qb = 15 - blockIdx.x;   // longest causal tiles first
    int bh = blockIdx.y;
    int t = threadIdx.x, wid=t>>5, lane=t&31;
    int wm = wid>>2, wn = wid&3;
    size_t rowbase = (size_t)bh*SS;
    size_t base = rowbase*DD;

    // Q splits: 4096 uint4
    {
        uint4* s4 = (uint4*)sm;
        const uint4* q4[2] = { (const uint4*)g_qH + (rowbase + qb*128)*16,
                               (const uint4*)g_qL + (rowbase + qb*128)*16 };
        #pragma unroll
        for (int i=0;i<16;i++){
            int slot = t + i*256;
            int sp = slot>>11, r = (slot>>4)&127, c16 = slot&15;
            s4[(sp*34816)/16 + r*17 + c16] = q4[sp][(size_t)r*16 + c16];
        }
    }
    if (t < 128){ mrow[t] = -INFINITY; lrow[t] = 0.f; }

    float oacc[4][4][4];
    #pragma unroll
    for (int mt=0;mt<4;mt++)
        #pragma unroll
        for (int nt=0;nt<4;nt++)
            #pragma unroll
            for (int e=0;e<4;e++) oacc[mt][nt][e]=0.f;
    __syncthreads();

    const float sscale = 0.08838834764831845f;
    uint32_t aRow = (uint32_t)(wm*64 + (lane&15));
    uint32_t aChk = (uint32_t)(lane>>4);
    uint32_t bRowS = (uint32_t)(wn*16 + (lane&7));   // S phase: n-tile 16
    uint32_t bRowV = (uint32_t)(wn*32 + (lane&7));   // PV phase: n-tile 32
    uint32_t bChk = (uint32_t)((lane>>3)&1);
    int rB = wm*64 + (lane>>2);
    int srow = t>>1, shalf = t&1;

    int jbmax = 2*qb + 1;
    for (int jb=0; jb<=jbmax; jb++){
        // K tiles: 2048 uint4
        {
            uint4* s4 = (uint4*)(sm + FK_H);
            const uint4* k4[2] = { (const uint4*)g_kH + (rowbase + jb*64)*16,
                                   (const uint4*)g_kL + (rowbase + jb*64)*16 };
            #pragma unroll
            for (int i=0;i<8;i++){
                int slot = t + i*256;
                int sp = slot>>10, r = (slot>>4)&63, c16 = slot&15;
                s4[(sp*17408)/16 + r*17 + c16] = k4[sp][(size_t)r*16 + c16];
            }
        }
        // VT tiles from pre-split transposed V: 2048 uint4
        #pragma unroll
        for (int i=0;i<8;i++){
            int slot = t + i*256;
            int sp = slot>>10, r = (slot>>3)&127, c = slot&7;
            const __nv_bfloat16* src = sp ? g_vTL : g_vTH;
            uint4 v = *(const uint4*)(src + (size_t)(bh*128+r)*2048 + jb*64 + c*8);
            *(uint4*)(sm + FVT_H + sp*18432 + r*144 + c*16) = v;
        }
        __syncthreads();

        // S = Q K^T (3-pass)
        float sacc[4][2][4];
        #pragma unroll
        for (int mt=0;mt<4;mt++)
            #pragma unroll
            for (int nt=0;nt<2;nt++)
                #pragma unroll
                for (int e=0;e<4;e++) sacc[mt][nt][e]=0.f;
        #pragma unroll
        for (int kf=0; kf<8; kf++){
            uint32_t aH[4][4], aL[4][4], bH[2][2], bL[2][2];
            #pragma unroll
            for (int mt=0;mt<4;mt++){
                uint32_t off = (aRow + mt*16)*272u + (kf*2 + aChk)*16u;
                ldsm_x4(aH[mt][0],aH[mt][1],aH[mt][2],aH[mt][3], sb + FQ_H + off);
                ldsm_x4(aL[mt][0],aL[mt][1],aL[mt][2],aL[mt][3], sb + FQ_L + off);
            }
            #pragma unroll
            for (int nt=0;nt<2;nt++){
                uint32_t off = (bRowS + nt*8)*272u + (kf*2 + bChk)*16u;
                ldsm_x2(bH[nt][0],bH[nt][1], sb + FK_H + off);
                ldsm_x2(bL[nt][0],bL[nt][1], sb + FK_L + off);
            }
            #pragma unroll
            for (int mt=0;mt<4;mt++)
                #pragma unroll
                for (int nt=0;nt<2;nt++){
                    mma_bf16(sacc[mt][nt], aH[mt], bH[nt]);
                    mma_bf16(sacc[mt][nt], aH[mt], bL[nt]);
                    mma_bf16(sacc[mt][nt], aL[mt], bH[nt]);
                }
        }
        // store S -> PS with mask & scale
        {
            int cBs = wn*16 + (lane&3)*2;
            #pragma unroll
            for (int mt=0;mt<4;mt++)
                #pragma unroll
                for (int nt=0;nt<2;nt++)
                    #pragma unroll
                    for (int half=0; half<2; half++){
                        int row = rB + mt*16 + half*8;
                        int col = cBs + nt*8;
                        int qrow = qb*128 + row, kcol = jb*64 + col;
                        PS[row*65+col]   = (kcol   <= qrow) ? sacc[mt][nt][half*2+0]*sscale : -INFINITY;
                        PS[row*65+col+1] = (kcol+1 <= qrow) ? sacc[mt][nt][half*2+1]*sscale : -INFINITY;
                    }
        }
        __syncthreads();

        // online softmax: 2 threads per row (each 32 cols), two-phase
        {
            float* PSrow = PS + srow*65 + shalf*32;
            float pm = -INFINITY;
            #pragma unroll 8
            for (int j=0;j<32;j++) pm = fmaxf(pm, PSrow[j]);
            scrA[t] = pm;
            __syncthreads();
            float m_new = fmaxf(mrow[srow], fmaxf(scrA[2*srow], scrA[2*srow+1]));
            float psum = 0.f;
            #pragma unroll 8
            for (int j=0;j<32;j++){
                float p = __expf(PSrow[j] - m_new);
                PSrow[j] = p;
                psum += p;
            }
            scrB[t] = psum;
            __syncthreads();
            if (t < 128){
                float mo = mrow[t];
                float mn = fmaxf(mo, fmaxf(scrA[2*t], scrA[2*t+1]));
                float sc = __expf(mo - mn);
                lrow[t] = sc*lrow[t] + scrB[2*t] + scrB[2*t+1];
                mrow[t] = mn;
                rs[t]   = sc;
            }
        }
        __syncthreads();

        // split P -> bf16 (stride 72)
        #pragma unroll
        for (int i=0;i<32;i++){
            int e = i*256 + t;
            int row = e>>6, col = e&63;
            __nv_bfloat16 h,l; bf16split(PS[row*65+col], h, l);
            PH[row*72+col] = h; PL[row*72+col] = l;
        }
        __syncthreads();

        // rescale O, then O += P V (3-pass)
        #pragma unroll
        for (int mt=0;mt<4;mt++){
            float s0 = rs[rB + mt*16], s1 = rs[rB + mt*16 + 8];
            #pragma unroll
            for (int nt=0;nt<4;nt++){
                oacc[mt][nt][0] *= s0; oacc[mt][nt][1] *= s0;
                oacc[mt][nt][2] *= s1; oacc[mt][nt][3] *= s1;
            }
        }
        #pragma unroll
        for (int kf=0; kf<4; kf++){
            uint32_t aH[4][4], aL[4][4], bH[4][2], bL[4][2];
            #pragma unroll
            for (int mt=0;mt<4;mt++){
                uint32_t off = (aRow + mt*16)*144u + (kf*2 + aChk)*16u;
                ldsm_x4(aH[mt][0],aH[mt][1],aH[mt][2],aH[mt][3], sb + FP_H + off);
                ldsm_x4(aL[mt][0],aL[mt][1],aL[mt][2],aL[mt][3], sb + FP_L + off);
            }
            #pragma unroll
            for (int nt=0;nt<4;nt++){
                uint32_t off = (bRowV + nt*8)*144u + (kf*2 + bChk)*16u;
                ldsm_x2(bH[nt][0],bH[nt][1], sb + FVT_H + off);
                ldsm_x2(bL[nt][0],bL[nt][1], sb + FVT_L + off);
            }
            #pragma unroll
            for (int mt=0;mt<4;mt++)
                #pragma unroll
                for (int nt=0;nt<4;nt++){
                    mma_bf16(oacc[mt][nt], aH[mt], bH[nt]);
                    mma_bf16(oacc[mt][nt], aH[mt], bL[nt]);
                    mma_bf16(oacc[mt][nt], aL[mt], bH[nt]);
                }
        }
        __syncthreads();
    }

    // final normalize + store
    int cB = wn*32 + (lane&3)*2;
    #pragma unroll
    for (int mt=0;mt<4;mt++)
        #pragma unroll
        for (int half=0; half<2; half++){
            int row = rB + mt*16 + half*8;
            float linv = 1.f/lrow[row];
            #pragma unroll
            for (int nt=0;nt<4;nt++){
                int col = cB + nt*8;
                size_t o = base + (size_t)(qb*128+row)*DD + col;
                g_att[o]   = oacc[mt][nt][half*2+0]*linv;
                g_att[o+1] = oacc[mt][nt][half*2+1]*linv;
            }
        }
}

// ---------------- M update via HMMA: partials per (h, 256-row chunk) ----------------
__global__ __launch_bounds__(256) void m_update_mma_kernel()
{
    __shared__ __nv_bfloat16 skTH[128*40], skTL[128*40], vTH[128*40], vTL[128*40];
    __shared__ float zred[256];
    uint32_t sA_H = smem_u32(skTH), sA_L = smem_u32(skTL);
    uint32_t sB_H = smem_u32(vTH),  sB_L = smem_u32(vTL);

    int h = blockIdx.x, c = blockIdx.y;
    int b = c>>3, s0 = (c&7)*256;
    size_t base = (((size_t)(b*HH + h))*SS + s0)*DD;
    int t = threadIdx.x, wid=t>>5, lane=t&31;
    int wm = wid>>2, wn = wid&3;

    float acc[4][4][4];
    #pragma unroll
    for (int mt=0;mt<4;mt++)
        #pragma unroll
        for (int nt=0;nt<4;nt++)
            #pragma unroll
            for (int e=0;e<4;e++) acc[mt][nt][e]=0.f;
    float zacc = 0.f;

    uint32_t aRow = (uint32_t)(wm*64 + (lane&15));
    uint32_t aChk = (uint32_t)(lane>>4);
    uint32_t bRow = (uint32_t)(wn*32 + (lane&7));
    uint32_t bChk = (uint32_t)((lane>>3)&1);

    for (int kc=0; kc<8; kc++){
        // transpose+split 32x128 chunks of sk and v
        #pragma unroll
        for (int i=0;i<16;i++){
            int e = i*256 + t;
            int s = e>>7, d = e&127;
            size_t g = base + (size_t)(kc*32+s)*DD + d;
            float sv = g_sk[g], vv = g_v[g];
            __nv_bfloat16 hh,ll;
            bf16split(sv,hh,ll); skTH[d*40+s]=hh; skTL[d*40+s]=ll;
            bf16split(vv,hh,ll); vTH[d*40+s]=hh;  vTL[d*40+s]=ll;
            zacc += sv;   // d = t&127, invariant per thread
        }
        __syncthreads();

        #pragma unroll
        for (int kf=0; kf<2; kf++){
            uint32_t aH[4][4], aL[4][4], bH[4][2], bL[4][2];
            #pragma unroll
            for (int mt=0;mt<4;mt++){
                uint32_t off = (aRow + mt*16)*80u + (kf*2 + aChk)*16u;
                ldsm_x4(aH[mt][0],aH[mt][1],aH[mt][2],aH[mt][3], sA_H + off);
                ldsm_x4(aL[mt][0],aL[mt][1],aL[mt][2],aL[mt][3], sA_L + off);
            }
            #pragma unroll
            for (int nt=0;nt<4;nt++){
                uint32_t off = (bRow + nt*8)*80u + (kf*2 + bChk)*16u;
                ldsm_x2(bH[nt][0],bH[nt][1], sB_H + off);
                ldsm_x2(bL[nt][0],bL[nt][1], sB_L + off);
            }
            #pragma unroll
            for (int mt=0;mt<4;mt++)
                #pragma unroll
                for (int nt=0;nt<4;nt++){
                    mma_bf16(acc[mt][nt], aH[mt], bH[nt]);
                    mma_bf16(acc[mt][nt], aH[mt], bL[nt]);
                    mma_bf16(acc[mt][nt], aL[mt], bH[nt]);
                }
        }
        __syncthreads();
    }

    zred[t] = zacc;
    __syncthreads();
    if (t < 128) g_zpart[(h*16 + c)*DD + t] = zred[t] + zred[t+128];

    size_t pbase = ((size_t)(h*16 + c)) << 14;
    int rB = wm*64 + (lane>>2);
    int cB = wn*32 + (lane&3)*2;
    #pragma unroll
    for (int mt=0;mt<4;mt++)
        #pragma unroll
        for (int nt=0;nt<4;nt++)
            #pragma unroll
            for (int half=0; half<2; half++){
                int row = rB + mt*16 + half*8;   // d
                int col = cB + nt*8;              // e
                g_mpart[pbase + (size_t)row*DD + col]   = acc[mt][nt][half*2+0];
                g_mpart[pbase + (size_t)row*DD + col+1] = acc[mt][nt][half*2+1];
            }
}

__global__ void reduce_m_kernel(const float* __restrict__ M, float* __restrict__ out)
{
    int idx = blockIdx.x*256 + threadIdx.x;
    int h = idx >> 14;
    int de = idx & 16383;
    float s = M[idx];
    #pragma unroll
    for (int c=0;c<16;c++) s += g_mpart[(((size_t)(h*16+c))<<14) + de];
    out[idx] = s;
}

__global__ void reduce_z_kernel(const float* __restrict__ z, float* __restrict__ out)
{
    int idx = blockIdx.x*256 + threadIdx.x;
    float s = z[idx];
    int h = idx >> 7, d = idx & 127;
    #pragma unroll
    for (int c=0;c<16;c++) s += g_zpart[(h*16+c)*DD + d];
    out[idx] = s;
}

// ---------------- launch ----------------
extern "C" void kernel_launch(void* const* d_in, const int* in_sizes, int n_in,
                              void* d_out, int out_size)
{
    (void)in_sizes; (void)n_in; (void)out_size;
    const float* hs   = (const float*)d_in[0];
    const float* Wq   = (const float*)d_in[1];
    const float* bq   = (const float*)d_in[2];
    const float* Wk   = (const float*)d_in[3];
    const float* bk   = (const float*)d_in[4];
    const float* Wv   = (const float*)d_in[5];
    const float* bv   = (const float*)d_in[6];
    const float* Wo   = (const float*)d_in[7];
    const float* beta = (const float*)d_in[8];
    const float* Mm   = (const float*)d_in[9];
    const float* zz   = (const float*)d_in[10];
    const int* pos    = (const int*)d_in[12];
    float* out = (float*)d_out;

    cudaFuncSetAttribute(attn_mma_kernel, cudaFuncAttributeMaxDynamicSharedMemorySize, FTOT);
    cudaFuncSetAttribute(memret_mma_kernel, cudaFuncAttributeMaxDynamicSharedMemorySize, 4*MR_TILE + 512);
    cudaFuncSetAttribute(gemm_mma_kernel, cudaFuncAttributeMaxDynamicSharedMemorySize, GEMM_SMEM);
    cudaFuncSetAttribute(vsplitT_kernel, cudaFuncAttributeMaxDynamicSharedMemorySize, VT_SMEM);

    // splits + transposes of inputs
    split_a_kernel<<<MTOT*HIDN/256, 256>>>(hs);
    wsplit_kernel<<<dim3(64,64,4), 256>>>(Wq, Wk, Wv, Wo);
    msplit_kernel<<<1024, 256>>>(Mm);

    // QKV (q->g_sq staging, k->g_sk staging, v->g_v)
    gemm_mma_kernel<<<dim3(16,32,3), 256, GEMM_SMEM>>>(bq, bk, bv, nullptr, 0);

    // rope: consumes staged q/k, emits bf16 splits + sigma
    rope_kernel<<<BHS/2, 256>>>(pos);

    // V transpose+split for attention PV
    vsplitT_kernel<<<dim3(32,16), 256, VT_SMEM>>>();

    den_kernel<<<BHS/8, 256>>>(zz);
    memret_mma_kernel<<<dim3(16,32), 256, 4*MR_TILE + 512>>>();

    attn_mma_kernel<<<dim3(16,32), 256, FTOT>>>();

    m_update_mma_kernel<<<dim3(16,16), 256>>>();
    reduce_m_kernel<<<1024, 256>>>(Mm, out + 8388608);
    reduce_z_kernel<<<8, 256>>>(zz, out + 8388608 + 262144);

    combine_split_kernel<<<MTOT*HIDN/256, 256>>>(beta);
    gemm_mma_kernel<<<dim3(16,32,1), 256, GEMM_SMEM>>>(bq, bk, bv, out, 1);
}